// round 1
// baseline (speedup 1.0000x reference)
#include <cuda_runtime.h>
#include <math.h>

// Problem constants: B=2, Tq=2048, Tctx=2048 -> Tk=4096, D=1024, H=16, hd=64
#define DMODEL 1024

// Persistent device scratch (allowed: static __device__ arrays, no runtime alloc)
__device__ float g_Q[2L * 2048 * 1024];   // 16 MB
__device__ float g_K[2L * 4096 * 1024];   // 32 MB
__device__ float g_V[2L * 4096 * 1024];   // 32 MB
__device__ float g_O[2L * 2048 * 1024];   // 16 MB

// ---------------------------------------------------------------------------
// Tiled fp32 GEMM with fused bias: C = A[M,K] @ W[K,N] + b
// Output row remap: crow = (m / 2048) * out_bstride + (m % 2048) + out_roff
// (lets us write the self/context halves of the concatenated K/V buffers)
// BM=BN=128, BK=8, 256 threads, 8x8 per thread. M,N,K multiples of 128 here.
// ---------------------------------------------------------------------------
__global__ void sgemm_bias_kernel(const float* __restrict__ A,
                                  const float* __restrict__ W,
                                  const float* __restrict__ bias,
                                  float* __restrict__ C,
                                  int M, int N, int K,
                                  int out_bstride, int out_roff)
{
    __shared__ float As[8][128];
    __shared__ float Bs[8][128];

    const int tid = threadIdx.x;
    const int tx = tid & 15;        // 0..15 -> N sub-tile
    const int ty = tid >> 4;        // 0..15 -> M sub-tile
    const int row0 = blockIdx.y * 128;
    const int col0 = blockIdx.x * 128;

    // A tile load: 128 rows x 8 cols = 256 float4 (2 per row), 1 per thread
    const int aRow  = tid >> 1;
    const int aCol4 = (tid & 1) << 2;
    // W tile load: 8 rows x 128 cols = 256 float4 (32 per row), 1 per thread
    const int bRow  = tid >> 5;
    const int bCol4 = (tid & 31) << 2;

    float acc[8][8];
#pragma unroll
    for (int i = 0; i < 8; i++)
#pragma unroll
        for (int j = 0; j < 8; j++) acc[i][j] = 0.f;

    for (int k0 = 0; k0 < K; k0 += 8) {
        float4 av = *reinterpret_cast<const float4*>(
            &A[(size_t)(row0 + aRow) * K + k0 + aCol4]);
        As[aCol4 + 0][aRow] = av.x;
        As[aCol4 + 1][aRow] = av.y;
        As[aCol4 + 2][aRow] = av.z;
        As[aCol4 + 3][aRow] = av.w;
        float4 wv = *reinterpret_cast<const float4*>(
            &W[(size_t)(k0 + bRow) * N + col0 + bCol4]);
        *reinterpret_cast<float4*>(&Bs[bRow][bCol4]) = wv;
        __syncthreads();

#pragma unroll
        for (int k = 0; k < 8; k++) {
            float4 ra0 = *reinterpret_cast<const float4*>(&As[k][ty * 8]);
            float4 ra1 = *reinterpret_cast<const float4*>(&As[k][ty * 8 + 4]);
            float4 rb0 = *reinterpret_cast<const float4*>(&Bs[k][tx * 8]);
            float4 rb1 = *reinterpret_cast<const float4*>(&Bs[k][tx * 8 + 4]);
            float ra[8] = {ra0.x, ra0.y, ra0.z, ra0.w, ra1.x, ra1.y, ra1.z, ra1.w};
            float rb[8] = {rb0.x, rb0.y, rb0.z, rb0.w, rb1.x, rb1.y, rb1.z, rb1.w};
#pragma unroll
            for (int i = 0; i < 8; i++)
#pragma unroll
                for (int j = 0; j < 8; j++)
                    acc[i][j] = fmaf(ra[i], rb[j], acc[i][j]);
        }
        __syncthreads();
    }

#pragma unroll
    for (int i = 0; i < 8; i++) {
        int m = row0 + ty * 8 + i;
        size_t crow = (size_t)((m >> 11) * out_bstride + (m & 2047) + out_roff);
#pragma unroll
        for (int j0 = 0; j0 < 8; j0 += 4) {
            int col = col0 + tx * 8 + j0;
            float4 bv = *reinterpret_cast<const float4*>(&bias[col]);
            float4 o;
            o.x = acc[i][j0 + 0] + bv.x;
            o.y = acc[i][j0 + 1] + bv.y;
            o.z = acc[i][j0 + 2] + bv.z;
            o.w = acc[i][j0 + 3] + bv.w;
            *reinterpret_cast<float4*>(&C[crow * N + col]) = o;
        }
    }
}

// ---------------------------------------------------------------------------
// Flash-attention (fp32 SIMT). One CTA per (batch, head, 64-row q-block).
// Streams K/V in 64-row blocks with online softmax. O lives in registers
// (4x4 per thread), P tile in smem, K/V share one smem buffer.
// Smem stride 65 to kill bank conflicts on column-style accesses.
// ---------------------------------------------------------------------------
__global__ void attn_kernel(const float* __restrict__ Q,
                            const float* __restrict__ K,
                            const float* __restrict__ V,
                            float* __restrict__ O)
{
    extern __shared__ float sm[];
    float* sQ   = sm;                  // 64*65
    float* sKV  = sQ + 64 * 65;        // 64*65
    float* sS   = sKV + 64 * 65;       // 64*65
    float* crow = sS + 64 * 65;        // 64
    float* lrow = crow + 64;           // 64

    const int tid = threadIdx.x;
    const int qb = blockIdx.x;   // 0..31
    const int h  = blockIdx.y;   // 0..15
    const int b  = blockIdx.z;   // 0..1
    const int q0 = qb * 64;
    const int D  = DMODEL;
    const float scale = 0.125f;  // 1/sqrt(64)

    const float* Qbase = Q + ((size_t)b * 2048 + q0) * D + h * 64;
    const float* Kbase = K + (size_t)b * 4096 * D + h * 64;
    const float* Vbase = V + (size_t)b * 4096 * D + h * 64;

    // Load + pre-scale Q block (64x64)
#pragma unroll
    for (int rep = 0; rep < 4; rep++) {
        int idx = tid + rep * 256;
        int r = idx >> 4, c = (idx & 15) << 2;
        float4 v = *reinterpret_cast<const float4*>(Qbase + (size_t)r * D + c);
        float* dst = &sQ[r * 65 + c];
        dst[0] = v.x * scale; dst[1] = v.y * scale;
        dst[2] = v.z * scale; dst[3] = v.w * scale;
    }

    const int srow = tid >> 2;   // softmax duty: row
    const int sg   = tid & 3;    // softmax duty: 16-col group
    float m_r = -1e30f, l_r = 0.f;

    const int ty = tid >> 4;     // 0..15: q-row group (4 rows)
    const int tx = tid & 15;     // 0..15: col group (4 cols)
    float oacc[4][4];
#pragma unroll
    for (int i = 0; i < 4; i++)
#pragma unroll
        for (int j = 0; j < 4; j++) oacc[i][j] = 0.f;

    for (int kb = 0; kb < 64; kb++) {
        // Load K block (64x64) into sKV
        const float* Kb = Kbase + (size_t)(kb * 64) * D;
#pragma unroll
        for (int rep = 0; rep < 4; rep++) {
            int idx = tid + rep * 256;
            int r = idx >> 4, c = (idx & 15) << 2;
            float4 v = *reinterpret_cast<const float4*>(Kb + (size_t)r * D + c);
            float* dst = &sKV[r * 65 + c];
            dst[0] = v.x; dst[1] = v.y; dst[2] = v.z; dst[3] = v.w;
        }
        __syncthreads();

        // S = (Q*scale) @ K^T  (thread: rows ty*4+i, cols tx*4+j)
        float acc[4][4];
#pragma unroll
        for (int i = 0; i < 4; i++)
#pragma unroll
            for (int j = 0; j < 4; j++) acc[i][j] = 0.f;
#pragma unroll
        for (int d = 0; d < 64; d++) {
            float qa[4], kk[4];
#pragma unroll
            for (int i = 0; i < 4; i++) qa[i] = sQ[(ty * 4 + i) * 65 + d];
#pragma unroll
            for (int j = 0; j < 4; j++) kk[j] = sKV[(tx * 4 + j) * 65 + d];
#pragma unroll
            for (int i = 0; i < 4; i++)
#pragma unroll
                for (int j = 0; j < 4; j++)
                    acc[i][j] = fmaf(qa[i], kk[j], acc[i][j]);
        }
#pragma unroll
        for (int i = 0; i < 4; i++)
#pragma unroll
            for (int j = 0; j < 4; j++)
                sS[(ty * 4 + i) * 65 + tx * 4 + j] = acc[i][j];
        __syncthreads();

        // Prefetch V block into registers (overlaps softmax)
        const float* Vb = Vbase + (size_t)(kb * 64) * D;
        float4 vbuf[4];
#pragma unroll
        for (int rep = 0; rep < 4; rep++) {
            int idx = tid + rep * 256;
            int r = idx >> 4, c = (idx & 15) << 2;
            vbuf[rep] = *reinterpret_cast<const float4*>(Vb + (size_t)r * D + c);
        }

        // Online softmax: 4 threads per row (consecutive lanes), shuffle-reduce
        float pm = -1e30f;
#pragma unroll
        for (int c = 0; c < 16; c++)
            pm = fmaxf(pm, sS[srow * 65 + sg * 16 + c]);
        pm = fmaxf(pm, __shfl_xor_sync(0xffffffffu, pm, 1));
        pm = fmaxf(pm, __shfl_xor_sync(0xffffffffu, pm, 2));
        float mnew = fmaxf(m_r, pm);
        float corr = __expf(m_r - mnew);
        float psum = 0.f;
#pragma unroll
        for (int c = 0; c < 16; c++) {
            float p = __expf(sS[srow * 65 + sg * 16 + c] - mnew);
            sS[srow * 65 + sg * 16 + c] = p;
            psum += p;
        }
        psum += __shfl_xor_sync(0xffffffffu, psum, 1);
        psum += __shfl_xor_sync(0xffffffffu, psum, 2);
        l_r = l_r * corr + psum;
        m_r = mnew;
        if (sg == 0) crow[srow] = corr;

        // Store V block into sKV (K reads were fenced by the prior sync)
#pragma unroll
        for (int rep = 0; rep < 4; rep++) {
            int idx = tid + rep * 256;
            int r = idx >> 4, c = (idx & 15) << 2;
            float* dst = &sKV[r * 65 + c];
            dst[0] = vbuf[rep].x; dst[1] = vbuf[rep].y;
            dst[2] = vbuf[rep].z; dst[3] = vbuf[rep].w;
        }
        __syncthreads();

        // O = O*corr + P @ V  (thread: rows ty*4+i, d-cols tx*4+j)
        float cf[4];
#pragma unroll
        for (int i = 0; i < 4; i++) cf[i] = crow[ty * 4 + i];
#pragma unroll
        for (int i = 0; i < 4; i++)
#pragma unroll
            for (int j = 0; j < 4; j++) oacc[i][j] *= cf[i];
#pragma unroll
        for (int c = 0; c < 64; c++) {
            float pv[4], vv[4];
#pragma unroll
            for (int i = 0; i < 4; i++) pv[i] = sS[(ty * 4 + i) * 65 + c];
#pragma unroll
            for (int j = 0; j < 4; j++) vv[j] = sKV[c * 65 + tx * 4 + j];
#pragma unroll
            for (int i = 0; i < 4; i++)
#pragma unroll
                for (int j = 0; j < 4; j++)
                    oacc[i][j] = fmaf(pv[i], vv[j], oacc[i][j]);
        }
        __syncthreads();
    }

    if (sg == 0) lrow[srow] = l_r;
    __syncthreads();

    float* Obase = O + ((size_t)b * 2048 + q0) * DMODEL + h * 64;
#pragma unroll
    for (int i = 0; i < 4; i++) {
        int r = ty * 4 + i;
        float inv = 1.f / lrow[r];
        float4 o4 = make_float4(oacc[i][0] * inv, oacc[i][1] * inv,
                                oacc[i][2] * inv, oacc[i][3] * inv);
        *reinterpret_cast<float4*>(Obase + (size_t)r * DMODEL + tx * 4) = o4;
    }
}

// ---------------------------------------------------------------------------
extern "C" void kernel_launch(void* const* d_in, const int* in_sizes, int n_in,
                              void* d_out, int out_size)
{
    const float* x   = (const float*)d_in[0];
    const float* ctx = (const float*)d_in[1];
    const float* Wq  = (const float*)d_in[2];
    const float* bq  = (const float*)d_in[3];
    const float* Wks = (const float*)d_in[4];
    const float* bks = (const float*)d_in[5];
    const float* Wvs = (const float*)d_in[6];
    const float* bvs = (const float*)d_in[7];
    const float* Wkc = (const float*)d_in[8];
    const float* bkc = (const float*)d_in[9];
    const float* Wvc = (const float*)d_in[10];
    const float* bvc = (const float*)d_in[11];
    const float* Wo  = (const float*)d_in[12];
    const float* bo  = (const float*)d_in[13];
    float* out = (float*)d_out;

    float *Qp, *Kp, *Vp, *Op;
    cudaGetSymbolAddress((void**)&Qp, g_Q);
    cudaGetSymbolAddress((void**)&Kp, g_K);
    cudaGetSymbolAddress((void**)&Vp, g_V);
    cudaGetSymbolAddress((void**)&Op, g_O);

    const int M = 4096, N = 1024, Kd = 1024;
    dim3 gblk(N / 128, M / 128);   // (8, 32)

    // Projections
    sgemm_bias_kernel<<<gblk, 256>>>(x,   Wq,  bq,  Qp, M, N, Kd, 2048, 0);
    sgemm_bias_kernel<<<gblk, 256>>>(x,   Wks, bks, Kp, M, N, Kd, 4096, 0);
    sgemm_bias_kernel<<<gblk, 256>>>(ctx, Wkc, bkc, Kp, M, N, Kd, 4096, 2048);
    sgemm_bias_kernel<<<gblk, 256>>>(x,   Wvs, bvs, Vp, M, N, Kd, 4096, 0);
    sgemm_bias_kernel<<<gblk, 256>>>(ctx, Wvc, bvc, Vp, M, N, Kd, 4096, 2048);

    // Attention
    size_t smem = (size_t)(3 * 64 * 65 + 128) * sizeof(float);  // 50432 B
    cudaFuncSetAttribute(attn_kernel,
                         cudaFuncAttributeMaxDynamicSharedMemorySize, (int)smem);
    dim3 agrid(32, 16, 2);
    attn_kernel<<<agrid, 256, smem>>>(Qp, Kp, Vp, Op);

    // Output projection
    sgemm_bias_kernel<<<gblk, 256>>>(Op, Wo, bo, out, M, N, Kd, 2048, 0);
}

// round 3
// speedup vs baseline: 4.4848x; 4.4848x over previous
#include <cuda_runtime.h>
#include <cuda_fp16.h>
#include <stdint.h>
#include <math.h>

// Shapes: B=2, Tq=2048, Tctx=2048 -> Tk=4096, D=1024, H=16, hd=64
// All projection GEMMs: M=4096, N=1024, K=1024.

#define GK 1024
#define GN 1024

// ---------------- persistent fp16 scratch ----------------
__device__ __half g_xh[4194304];            // x fp16    [4096][1024]
__device__ __half g_ch[4194304];            // ctx fp16  [4096][1024]
__device__ __half g_Wt[6][1048576];         // W^T fp16  [1024 n][1024 k]
__device__ __half g_Qh[4194304];            // Q (scaled)[2*2048][1024]
__device__ __half g_Kh[8388608];            // K concat  [2*4096][1024]
__device__ __half g_Vh[8388608];            // V concat  [2*4096][1024]
__device__ __half g_Oh[4194304];            // attn out  [2*2048][1024]

// ---------------- small helpers ----------------
__device__ __forceinline__ uint32_t smem_u32(const void* p) {
    return static_cast<uint32_t>(__cvta_generic_to_shared(p));
}
__device__ __forceinline__ void ldsm_x4(uint32_t* r, uint32_t addr) {
    asm volatile("ldmatrix.sync.aligned.m8n8.x4.shared.b16 {%0,%1,%2,%3}, [%4];"
                 : "=r"(r[0]), "=r"(r[1]), "=r"(r[2]), "=r"(r[3]) : "r"(addr));
}
__device__ __forceinline__ void ldsm_x2(uint32_t* r, uint32_t addr) {
    asm volatile("ldmatrix.sync.aligned.m8n8.x2.shared.b16 {%0,%1}, [%2];"
                 : "=r"(r[0]), "=r"(r[1]) : "r"(addr));
}
__device__ __forceinline__ void ldsm_x2t(uint32_t* r, uint32_t addr) {
    asm volatile("ldmatrix.sync.aligned.m8n8.x2.trans.shared.b16 {%0,%1}, [%2];"
                 : "=r"(r[0]), "=r"(r[1]) : "r"(addr));
}
__device__ __forceinline__ void mma16816(float* c, const uint32_t* a, const uint32_t* b) {
    asm volatile(
        "mma.sync.aligned.m16n8k16.row.col.f32.f16.f16.f32 "
        "{%0,%1,%2,%3}, {%4,%5,%6,%7}, {%8,%9}, {%0,%1,%2,%3};"
        : "+f"(c[0]), "+f"(c[1]), "+f"(c[2]), "+f"(c[3])
        : "r"(a[0]), "r"(a[1]), "r"(a[2]), "r"(a[3]), "r"(b[0]), "r"(b[1]));
}
__device__ __forceinline__ uint32_t pack_h2(float lo, float hi) {
    __half2 h;
    h.x = __float2half_rn(lo);
    h.y = __float2half_rn(hi);
    uint32_t u;
    memcpy(&u, &h, 4);
    return u;
}

// ---------------- fp32 -> fp16 convert ----------------
__global__ void f2h_kernel(const float* __restrict__ in, __half* __restrict__ out, int n4) {
    int i = blockIdx.x * blockDim.x + threadIdx.x;
    if (i < n4) {
        float4 v = reinterpret_cast<const float4*>(in)[i];
        __half2 a; a.x = __float2half_rn(v.x); a.y = __float2half_rn(v.y);
        __half2 b; b.x = __float2half_rn(v.z); b.y = __float2half_rn(v.w);
        reinterpret_cast<__half2*>(out)[i * 2]     = a;
        reinterpret_cast<__half2*>(out)[i * 2 + 1] = b;
    }
}

// ---------------- W [K][N] fp32 -> Wt [N][K] fp16 ----------------
__global__ void wtrans_kernel(const float* __restrict__ W, __half* __restrict__ Wt) {
    __shared__ float t[32][33];
    int n0 = blockIdx.x * 32, k0 = blockIdx.y * 32;
    int tx = threadIdx.x, ty = threadIdx.y;
#pragma unroll
    for (int i = 0; i < 32; i += 8)
        t[ty + i][tx] = W[(size_t)(k0 + ty + i) * GN + n0 + tx];
    __syncthreads();
#pragma unroll
    for (int i = 0; i < 32; i += 8)
        Wt[(size_t)(n0 + ty + i) * GK + k0 + tx] = __float2half_rn(t[tx][ty + i]);
}

// ---------------- HMMA GEMM: C[M=4096,1024] = A @ Wt^T + bias, x scale ----
// 128x128 CTA tile, BK=32, 8 warps (2m x 4n), warp tile 64x32.
// f32out: 0 -> fp16 store to outH, 1 -> fp32 store to outF.
__global__ __launch_bounds__(256) void hgemm_kernel(
    const __half* __restrict__ A, const __half* __restrict__ Bt,
    const float* __restrict__ bias, __half* __restrict__ outH,
    float* __restrict__ outF, int f32out, int bstride, int roff, float scale)
{
    __shared__ __half As[2][128][40];
    __shared__ __half Bs[2][128][40];

    const int tid = threadIdx.x;
    const int lane = tid & 31;
    const int wid = tid >> 5;
    const int wm = (wid >> 2) * 64;
    const int wn = (wid & 3) * 32;
    const int row0 = blockIdx.y * 128;
    const int col0 = blockIdx.x * 128;

    const int lr = tid & 127;          // smem row
    const int lc = (tid >> 7) * 16;    // 0 or 16
    const __half* Ag = A  + (size_t)(row0 + lr) * GK + lc;
    const __half* Bg = Bt + (size_t)(col0 + lr) * GK + lc;

    float acc[4][4][4];
#pragma unroll
    for (int i = 0; i < 4; i++)
#pragma unroll
        for (int j = 0; j < 4; j++)
#pragma unroll
            for (int k = 0; k < 4; k++) acc[i][j][k] = 0.f;

    const uint32_t sA = smem_u32(&As[0][0][0]);
    const uint32_t sB = smem_u32(&Bs[0][0][0]);

    // preload chunk 0
    uint4 av0 = *reinterpret_cast<const uint4*>(Ag);
    uint4 av1 = *reinterpret_cast<const uint4*>(Ag + 8);
    uint4 bv0 = *reinterpret_cast<const uint4*>(Bg);
    uint4 bv1 = *reinterpret_cast<const uint4*>(Bg + 8);
    *reinterpret_cast<uint4*>(&As[0][lr][lc])     = av0;
    *reinterpret_cast<uint4*>(&As[0][lr][lc + 8]) = av1;
    *reinterpret_cast<uint4*>(&Bs[0][lr][lc])     = bv0;
    *reinterpret_cast<uint4*>(&Bs[0][lr][lc + 8]) = bv1;
    __syncthreads();

    for (int c = 0; c < 32; c++) {
        const int cur = c & 1;
        if (c < 31) {
            const __half* An = Ag + (c + 1) * 32;
            const __half* Bn = Bg + (c + 1) * 32;
            av0 = *reinterpret_cast<const uint4*>(An);
            av1 = *reinterpret_cast<const uint4*>(An + 8);
            bv0 = *reinterpret_cast<const uint4*>(Bn);
            bv1 = *reinterpret_cast<const uint4*>(Bn + 8);
        }
#pragma unroll
        for (int ks = 0; ks < 2; ks++) {
            uint32_t af[4][4];
#pragma unroll
            for (int mt = 0; mt < 4; mt++) {
                int row = wm + mt * 16 + (lane & 7) + (lane & 8);
                int col = ks * 16 + (lane >> 4) * 8;
                ldsm_x4(af[mt], sA + ((cur * 128 + row) * 40 + col) * 2);
            }
            uint32_t bf[4][2];
#pragma unroll
            for (int nt = 0; nt < 4; nt++) {
                int l2 = lane & 15;
                int row = wn + nt * 8 + (l2 & 7);
                int col = ks * 16 + (l2 >> 3) * 8;
                ldsm_x2(bf[nt], sB + ((cur * 128 + row) * 40 + col) * 2);
            }
#pragma unroll
            for (int mt = 0; mt < 4; mt++)
#pragma unroll
                for (int nt = 0; nt < 4; nt++)
                    mma16816(acc[mt][nt], af[mt], bf[nt]);
        }
        if (c < 31) {
            const int nxt = cur ^ 1;
            *reinterpret_cast<uint4*>(&As[nxt][lr][lc])     = av0;
            *reinterpret_cast<uint4*>(&As[nxt][lr][lc + 8]) = av1;
            *reinterpret_cast<uint4*>(&Bs[nxt][lr][lc])     = bv0;
            *reinterpret_cast<uint4*>(&Bs[nxt][lr][lc + 8]) = bv1;
        }
        __syncthreads();
    }

    // epilogue: bias + scale, store fp16 or fp32
    const int g = lane >> 2;
    const int qd = lane & 3;
#pragma unroll
    for (int mt = 0; mt < 4; mt++) {
        int r0 = row0 + wm + mt * 16 + g;
        int r1 = r0 + 8;
        size_t or0 = (size_t)((r0 >> 11) * bstride + (r0 & 2047) + roff);
        size_t or1 = (size_t)((r1 >> 11) * bstride + (r1 & 2047) + roff);
#pragma unroll
        for (int nt = 0; nt < 4; nt++) {
            int col = col0 + wn + nt * 8 + qd * 2;
            float b0 = bias[col];
            float b1 = bias[col + 1];
            float v00 = (acc[mt][nt][0] + b0) * scale;
            float v01 = (acc[mt][nt][1] + b1) * scale;
            float v10 = (acc[mt][nt][2] + b0) * scale;
            float v11 = (acc[mt][nt][3] + b1) * scale;
            if (f32out) {
                outF[or0 * GN + col]     = v00;
                outF[or0 * GN + col + 1] = v01;
                outF[or1 * GN + col]     = v10;
                outF[or1 * GN + col + 1] = v11;
            } else {
                *reinterpret_cast<uint32_t*>(&outH[or0 * GN + col]) = pack_h2(v00, v01);
                *reinterpret_cast<uint32_t*>(&outH[or1 * GN + col]) = pack_h2(v10, v11);
            }
        }
    }
}

// ---------------- flash attention (HMMA) ----------------
// CTA: 128 q-rows x (b,h); 8 warps, warp = 16 q-rows. K/V streamed in
// 64-key blocks. Q pre-scaled by 0.125*log2(e); softmax via exp2f.
__global__ __launch_bounds__(256) void attn_hmma_kernel(
    const __half* __restrict__ Q, const __half* __restrict__ K,
    const __half* __restrict__ V, __half* __restrict__ O)
{
    __shared__ __half Ks[64][72];
    __shared__ __half Vs[64][72];

    const int tid = threadIdx.x;
    const int lane = tid & 31;
    const int wid = tid >> 5;
    const int qt = blockIdx.x;
    const int h = blockIdx.y;
    const int b = blockIdx.z;
    const int q0 = qt * 128 + wid * 16;
    const int g = lane >> 2;
    const int qd = lane & 3;
    const int l2 = lane & 15;

    const __half* Qb = Q + ((size_t)b * 2048 + q0) * GN + h * 64;
    const __half* Kb = K + (size_t)b * 4096 * GN + h * 64;
    const __half* Vb = V + (size_t)b * 4096 * GN + h * 64;

    // Q fragments (A operand), loaded once straight from gmem
    uint32_t qf[4][4];
#pragma unroll
    for (int ks = 0; ks < 4; ks++) {
        int c0 = ks * 16 + qd * 2;
        qf[ks][0] = *reinterpret_cast<const uint32_t*>(Qb + (size_t)g * GN + c0);
        qf[ks][1] = *reinterpret_cast<const uint32_t*>(Qb + (size_t)(g + 8) * GN + c0);
        qf[ks][2] = *reinterpret_cast<const uint32_t*>(Qb + (size_t)g * GN + c0 + 8);
        qf[ks][3] = *reinterpret_cast<const uint32_t*>(Qb + (size_t)(g + 8) * GN + c0 + 8);
    }

    float of[8][4];
#pragma unroll
    for (int i = 0; i < 8; i++)
#pragma unroll
        for (int j = 0; j < 4; j++) of[i][j] = 0.f;
    float m0 = -1e30f, m1 = -1e30f, l0 = 0.f, l1 = 0.f;

    const uint32_t sK = smem_u32(&Ks[0][0]);
    const uint32_t sV = smem_u32(&Vs[0][0]);
    const int lr = tid & 63;
    const int lc = (tid >> 6) * 16;

    for (int kb = 0; kb < 64; kb++) {
        const __half* Kg = Kb + (size_t)(kb * 64 + lr) * GN + lc;
        const __half* Vg = Vb + (size_t)(kb * 64 + lr) * GN + lc;
        uint4 k0v = *reinterpret_cast<const uint4*>(Kg);
        uint4 k1v = *reinterpret_cast<const uint4*>(Kg + 8);
        uint4 v0v = *reinterpret_cast<const uint4*>(Vg);
        uint4 v1v = *reinterpret_cast<const uint4*>(Vg + 8);
        __syncthreads();   // previous block's smem reads done
        *reinterpret_cast<uint4*>(&Ks[lr][lc])     = k0v;
        *reinterpret_cast<uint4*>(&Ks[lr][lc + 8]) = k1v;
        *reinterpret_cast<uint4*>(&Vs[lr][lc])     = v0v;
        *reinterpret_cast<uint4*>(&Vs[lr][lc + 8]) = v1v;
        __syncthreads();

        // S = Qs @ K^T : 8 key-tiles of 8, 4 d-steps of 16
        float sc[8][4];
#pragma unroll
        for (int nt = 0; nt < 8; nt++) {
            sc[nt][0] = 0.f; sc[nt][1] = 0.f; sc[nt][2] = 0.f; sc[nt][3] = 0.f;
#pragma unroll
            for (int ks = 0; ks < 4; ks++) {
                uint32_t bf[2];
                int row = nt * 8 + (l2 & 7);
                int col = ks * 16 + (l2 >> 3) * 8;
                ldsm_x2(bf, sK + (row * 72 + col) * 2);
                mma16816(sc[nt], qf[ks], bf);
            }
        }

        // online softmax (rows g and g+8; quad lanes share a row)
        float mx0 = -1e30f, mx1 = -1e30f;
#pragma unroll
        for (int nt = 0; nt < 8; nt++) {
            mx0 = fmaxf(mx0, fmaxf(sc[nt][0], sc[nt][1]));
            mx1 = fmaxf(mx1, fmaxf(sc[nt][2], sc[nt][3]));
        }
        mx0 = fmaxf(mx0, __shfl_xor_sync(0xffffffffu, mx0, 1));
        mx0 = fmaxf(mx0, __shfl_xor_sync(0xffffffffu, mx0, 2));
        mx1 = fmaxf(mx1, __shfl_xor_sync(0xffffffffu, mx1, 1));
        mx1 = fmaxf(mx1, __shfl_xor_sync(0xffffffffu, mx1, 2));
        float nm0 = fmaxf(m0, mx0);
        float nm1 = fmaxf(m1, mx1);
        float cr0 = exp2f(m0 - nm0);
        float cr1 = exp2f(m1 - nm1);
        float s0 = 0.f, s1 = 0.f;
#pragma unroll
        for (int nt = 0; nt < 8; nt++) {
            sc[nt][0] = exp2f(sc[nt][0] - nm0);
            sc[nt][1] = exp2f(sc[nt][1] - nm0);
            sc[nt][2] = exp2f(sc[nt][2] - nm1);
            sc[nt][3] = exp2f(sc[nt][3] - nm1);
            s0 += sc[nt][0] + sc[nt][1];
            s1 += sc[nt][2] + sc[nt][3];
        }
        s0 += __shfl_xor_sync(0xffffffffu, s0, 1);
        s0 += __shfl_xor_sync(0xffffffffu, s0, 2);
        s1 += __shfl_xor_sync(0xffffffffu, s1, 1);
        s1 += __shfl_xor_sync(0xffffffffu, s1, 2);
        l0 = l0 * cr0 + s0;
        l1 = l1 * cr1 + s1;
        m0 = nm0;
        m1 = nm1;
#pragma unroll
        for (int dn = 0; dn < 8; dn++) {
            of[dn][0] *= cr0; of[dn][1] *= cr0;
            of[dn][2] *= cr1; of[dn][3] *= cr1;
        }

        // pack P (fp16) into A-fragments for P@V
        uint32_t pf[4][4];
#pragma unroll
        for (int kp = 0; kp < 4; kp++) {
            pf[kp][0] = pack_h2(sc[2 * kp][0],     sc[2 * kp][1]);
            pf[kp][1] = pack_h2(sc[2 * kp][2],     sc[2 * kp][3]);
            pf[kp][2] = pack_h2(sc[2 * kp + 1][0], sc[2 * kp + 1][1]);
            pf[kp][3] = pack_h2(sc[2 * kp + 1][2], sc[2 * kp + 1][3]);
        }

        // O += P @ V : 8 d-tiles of 8, 4 key-steps of 16
#pragma unroll
        for (int dn = 0; dn < 8; dn++)
#pragma unroll
            for (int kp = 0; kp < 4; kp++) {
                uint32_t bf[2];
                ldsm_x2t(bf, sV + ((kp * 16 + l2) * 72 + dn * 8) * 2);
                mma16816(of[dn], pf[kp], bf);
            }
    }

    // epilogue
    float inv0 = 1.f / l0;
    float inv1 = 1.f / l1;
    __half* Ob = O + ((size_t)b * 2048 + q0) * GN + h * 64;
#pragma unroll
    for (int dn = 0; dn < 8; dn++) {
        int col = dn * 8 + qd * 2;
        *reinterpret_cast<uint32_t*>(Ob + (size_t)g * GN + col) =
            pack_h2(of[dn][0] * inv0, of[dn][1] * inv0);
        *reinterpret_cast<uint32_t*>(Ob + (size_t)(g + 8) * GN + col) =
            pack_h2(of[dn][2] * inv1, of[dn][3] * inv1);
    }
}

// ---------------------------------------------------------------------------
extern "C" void kernel_launch(void* const* d_in, const int* in_sizes, int n_in,
                              void* d_out, int out_size)
{
    const float* x   = (const float*)d_in[0];
    const float* ctx = (const float*)d_in[1];
    const float* W0  = (const float*)d_in[2];   // Wq
    const float* b0  = (const float*)d_in[3];
    const float* W1  = (const float*)d_in[4];   // Wks
    const float* b1  = (const float*)d_in[5];
    const float* W2  = (const float*)d_in[6];   // Wvs
    const float* b2  = (const float*)d_in[7];
    const float* W3  = (const float*)d_in[8];   // Wkc
    const float* b3  = (const float*)d_in[9];
    const float* W4  = (const float*)d_in[10];  // Wvc
    const float* b4  = (const float*)d_in[11];
    const float* W5  = (const float*)d_in[12];  // Wo
    const float* b5  = (const float*)d_in[13];
    float* out = (float*)d_out;

    __half* xh;
    __half* ch;
    __half* Wt;
    __half* Qh;
    __half* Kh;
    __half* Vh;
    __half* Oh;
    cudaGetSymbolAddress((void**)&xh, g_xh);
    cudaGetSymbolAddress((void**)&ch, g_ch);
    cudaGetSymbolAddress((void**)&Wt, g_Wt);
    cudaGetSymbolAddress((void**)&Qh, g_Qh);
    cudaGetSymbolAddress((void**)&Kh, g_Kh);
    cudaGetSymbolAddress((void**)&Vh, g_Vh);
    cudaGetSymbolAddress((void**)&Oh, g_Oh);

    // fp32 -> fp16 inputs
    f2h_kernel<<<4096, 256>>>(x,   xh, 1048576);
    f2h_kernel<<<4096, 256>>>(ctx, ch, 1048576);

    // weights: transpose-convert to [N][K] fp16
    dim3 wgrid(32, 32);
    dim3 wblk(32, 8);
    wtrans_kernel<<<wgrid, wblk>>>(W0, Wt + 0u * 1048576u);
    wtrans_kernel<<<wgrid, wblk>>>(W1, Wt + 1u * 1048576u);
    wtrans_kernel<<<wgrid, wblk>>>(W2, Wt + 2u * 1048576u);
    wtrans_kernel<<<wgrid, wblk>>>(W3, Wt + 3u * 1048576u);
    wtrans_kernel<<<wgrid, wblk>>>(W4, Wt + 4u * 1048576u);
    wtrans_kernel<<<wgrid, wblk>>>(W5, Wt + 5u * 1048576u);

    dim3 ggrid(8, 32);  // N/128, M/128
    const float qscale = 0.125f * 1.4426950408889634f;  // 1/sqrt(hd) * log2(e)

    // projections
    hgemm_kernel<<<ggrid, 256>>>(xh, Wt + 0u * 1048576u, b0, Qh, nullptr, 0, 2048, 0,    qscale);
    hgemm_kernel<<<ggrid, 256>>>(xh, Wt + 1u * 1048576u, b1, Kh, nullptr, 0, 4096, 0,    1.0f);
    hgemm_kernel<<<ggrid, 256>>>(ch, Wt + 3u * 1048576u, b3, Kh, nullptr, 0, 4096, 2048, 1.0f);
    hgemm_kernel<<<ggrid, 256>>>(xh, Wt + 2u * 1048576u, b2, Vh, nullptr, 0, 4096, 0,    1.0f);
    hgemm_kernel<<<ggrid, 256>>>(ch, Wt + 4u * 1048576u, b4, Vh, nullptr, 0, 4096, 2048, 1.0f);

    // attention
    dim3 agrid(16, 16, 2);
    attn_hmma_kernel<<<agrid, 256>>>(Qh, Kh, Vh, Oh);

    // output projection (fp32 out)
    hgemm_kernel<<<ggrid, 256>>>(Oh, Wt + 5u * 1048576u, b5, nullptr, out, 1, 2048, 0, 1.0f);
}

// round 5
// speedup vs baseline: 5.5436x; 1.2361x over previous
#include <cuda_runtime.h>
#include <cuda_fp16.h>
#include <stdint.h>
#include <math.h>

// Shapes: B=2, Tq=2048, Tctx=2048 -> Tk=4096, D=1024, H=16, hd=64
// All projection GEMMs: M=4096, N=1024, K=1024.

#define GK 1024
#define GN 1024

// ---------------- persistent fp16 scratch ----------------
__device__ __half g_xh[4194304];            // x fp16    [4096][1024]
__device__ __half g_ch[4194304];            // ctx fp16  [4096][1024]
__device__ __half g_Wt[6][1048576];         // W^T fp16  [1024 n][1024 k]
__device__ __half g_Qh[4194304];            // Q (scaled)[2*2048][1024]
__device__ __half g_Kh[8388608];            // K concat  [2*4096][1024]
__device__ __half g_Vh[8388608];            // V concat  [2*4096][1024]
__device__ __half g_Oh[4194304];            // attn out  [2*2048][1024]

// ---------------- ptx helpers ----------------
__device__ __forceinline__ uint32_t smem_u32(const void* p) {
    return static_cast<uint32_t>(__cvta_generic_to_shared(p));
}
__device__ __forceinline__ void cp16(uint32_t dst, const void* src) {
    asm volatile("cp.async.cg.shared.global [%0], [%1], 16;" :: "r"(dst), "l"(src));
}
__device__ __forceinline__ void cp_commit() {
    asm volatile("cp.async.commit_group;" ::: "memory");
}
__device__ __forceinline__ void cp_wait1() {
    asm volatile("cp.async.wait_group 1;" ::: "memory");
}
__device__ __forceinline__ void cp_wait0() {
    asm volatile("cp.async.wait_group 0;" ::: "memory");
}
__device__ __forceinline__ void ldsm_x4(uint32_t* r, uint32_t addr) {
    asm volatile("ldmatrix.sync.aligned.m8n8.x4.shared.b16 {%0,%1,%2,%3}, [%4];"
                 : "=r"(r[0]), "=r"(r[1]), "=r"(r[2]), "=r"(r[3]) : "r"(addr));
}
__device__ __forceinline__ void ldsm_x2(uint32_t* r, uint32_t addr) {
    asm volatile("ldmatrix.sync.aligned.m8n8.x2.shared.b16 {%0,%1}, [%2];"
                 : "=r"(r[0]), "=r"(r[1]) : "r"(addr));
}
__device__ __forceinline__ void ldsm_x2t(uint32_t* r, uint32_t addr) {
    asm volatile("ldmatrix.sync.aligned.m8n8.x2.trans.shared.b16 {%0,%1}, [%2];"
                 : "=r"(r[0]), "=r"(r[1]) : "r"(addr));
}
__device__ __forceinline__ void mma16816(float* c, const uint32_t* a, const uint32_t* b) {
    asm volatile(
        "mma.sync.aligned.m16n8k16.row.col.f32.f16.f16.f32 "
        "{%0,%1,%2,%3}, {%4,%5,%6,%7}, {%8,%9}, {%0,%1,%2,%3};"
        : "+f"(c[0]), "+f"(c[1]), "+f"(c[2]), "+f"(c[3])
        : "r"(a[0]), "r"(a[1]), "r"(a[2]), "r"(a[3]), "r"(b[0]), "r"(b[1]));
}
__device__ __forceinline__ uint32_t pack_h2(float lo, float hi) {
    __half2 h;
    h.x = __float2half_rn(lo);
    h.y = __float2half_rn(hi);
    uint32_t u;
    memcpy(&u, &h, 4);
    return u;
}

// ---------------- fp32 -> fp16 convert ----------------
__global__ void f2h_kernel(const float* __restrict__ in, __half* __restrict__ out, int n4) {
    int i = blockIdx.x * blockDim.x + threadIdx.x;
    if (i < n4) {
        float4 v = reinterpret_cast<const float4*>(in)[i];
        __half2 a; a.x = __float2half_rn(v.x); a.y = __float2half_rn(v.y);
        __half2 b; b.x = __float2half_rn(v.z); b.y = __float2half_rn(v.w);
        reinterpret_cast<__half2*>(out)[i * 2]     = a;
        reinterpret_cast<__half2*>(out)[i * 2 + 1] = b;
    }
}

// ---------------- W [K][N] fp32 -> Wt [N][K] fp16 ----------------
__global__ void wtrans_kernel(const float* __restrict__ W, __half* __restrict__ Wt) {
    __shared__ float t[32][33];
    int n0 = blockIdx.x * 32, k0 = blockIdx.y * 32;
    int tx = threadIdx.x, ty = threadIdx.y;
#pragma unroll
    for (int i = 0; i < 32; i += 8)
        t[ty + i][tx] = W[(size_t)(k0 + ty + i) * GN + n0 + tx];
    __syncthreads();
#pragma unroll
    for (int i = 0; i < 32; i += 8)
        Wt[(size_t)(n0 + ty + i) * GK + k0 + tx] = __float2half_rn(t[tx][ty + i]);
}

// ---------------- HMMA GEMM, 3-stage cp.async pipeline ----------------
// C[4096,1024] = A @ Wt^T + bias, x scale. 128x128 CTA tile, BK=32,
// 8 warps (2m x 4n), warp tile 64x32. Dynamic smem: 3 stages x (A+B) tiles,
// each tile 128 rows x 40 halves (80 B/row, 16B-aligned since 80 = 5*16).
#define TSZ 10240                 // one tile: 128 * 40 * 2 bytes
#define A_OFF(s) ((s) * TSZ)
#define B_OFF(s) (3 * TSZ + (s) * TSZ)
#define SM_GEMM (6 * TSZ)         // 61440 bytes

__global__ __launch_bounds__(256) void hgemm_kernel(
    const __half* __restrict__ A, const __half* __restrict__ Bt,
    const float* __restrict__ bias, __half* __restrict__ outH,
    float* __restrict__ outF, int f32out, int bstride, int roff, float scale)
{
    extern __shared__ char smem[];
    const uint32_t sb = smem_u32(smem);

    const int tid = threadIdx.x;
    const int lane = tid & 31;
    const int wid = tid >> 5;
    const int wm = (wid >> 2) * 64;
    const int wn = (wid & 3) * 32;
    const int row0 = blockIdx.y * 128;
    const int col0 = blockIdx.x * 128;

    const __half* Ag = A + (size_t)row0 * GK;
    const __half* Bg = Bt + (size_t)col0 * GK;

    // per chunk: A tile 128x32 halves = 512 x 16B, B same; 2+2 cp16 per thread
#define GLOAD(kc, s)                                                         \
    {                                                                        \
        _Pragma("unroll")                                                    \
        for (int j = 0; j < 2; j++) {                                        \
            int idx = tid + j * 256;                                         \
            int r = idx >> 2;                                                \
            int cb = (idx & 3) * 8;                                          \
            cp16(sb + A_OFF(s) + r * 80 + cb * 2,                            \
                 Ag + (size_t)r * GK + (kc) * 32 + cb);                      \
            cp16(sb + B_OFF(s) + r * 80 + cb * 2,                            \
                 Bg + (size_t)r * GK + (kc) * 32 + cb);                      \
        }                                                                    \
    }

    float acc[4][4][4];
#pragma unroll
    for (int i = 0; i < 4; i++)
#pragma unroll
        for (int j = 0; j < 4; j++)
#pragma unroll
            for (int k = 0; k < 4; k++) acc[i][j][k] = 0.f;

    GLOAD(0, 0); cp_commit();
    GLOAD(1, 1); cp_commit();

    for (int c = 0; c < 32; c++) {
        const int s = c % 3;
        cp_wait1();
        __syncthreads();
        if (c + 2 < 32) GLOAD(c + 2, (c + 2) % 3);
        cp_commit();   // always commit (empty groups keep accounting uniform)

#pragma unroll
        for (int ks = 0; ks < 2; ks++) {
            uint32_t af[4][4];
#pragma unroll
            for (int mt = 0; mt < 4; mt++) {
                int row = wm + mt * 16 + (lane & 7) + (lane & 8);
                int col = ks * 16 + (lane >> 4) * 8;
                ldsm_x4(af[mt], sb + A_OFF(s) + (row * 40 + col) * 2);
            }
            uint32_t bf[4][2];
#pragma unroll
            for (int nt = 0; nt < 4; nt++) {
                int l2 = lane & 15;
                int row = wn + nt * 8 + (l2 & 7);
                int col = ks * 16 + (l2 >> 3) * 8;
                ldsm_x2(bf[nt], sb + B_OFF(s) + (row * 40 + col) * 2);
            }
#pragma unroll
            for (int mt = 0; mt < 4; mt++)
#pragma unroll
                for (int nt = 0; nt < 4; nt++)
                    mma16816(acc[mt][nt], af[mt], bf[nt]);
        }
    }

    // epilogue: bias + scale, store fp16 or fp32
    const int g = lane >> 2;
    const int qd = lane & 3;
#pragma unroll
    for (int mt = 0; mt < 4; mt++) {
        int r0 = row0 + wm + mt * 16 + g;
        int r1 = r0 + 8;
        size_t or0 = (size_t)((r0 >> 11) * bstride + (r0 & 2047) + roff);
        size_t or1 = (size_t)((r1 >> 11) * bstride + (r1 & 2047) + roff);
#pragma unroll
        for (int nt = 0; nt < 4; nt++) {
            int col = col0 + wn + nt * 8 + qd * 2;
            float b0 = bias[col];
            float b1 = bias[col + 1];
            float v00 = (acc[mt][nt][0] + b0) * scale;
            float v01 = (acc[mt][nt][1] + b1) * scale;
            float v10 = (acc[mt][nt][2] + b0) * scale;
            float v11 = (acc[mt][nt][3] + b1) * scale;
            if (f32out) {
                outF[or0 * GN + col]     = v00;
                outF[or0 * GN + col + 1] = v01;
                outF[or1 * GN + col]     = v10;
                outF[or1 * GN + col + 1] = v11;
            } else {
                *reinterpret_cast<uint32_t*>(&outH[or0 * GN + col]) = pack_h2(v00, v01);
                *reinterpret_cast<uint32_t*>(&outH[or1 * GN + col]) = pack_h2(v10, v11);
            }
        }
    }
}

// ---------------- flash attention (HMMA, cp.async double-buffered K/V) ------
__global__ __launch_bounds__(256) void attn_hmma_kernel(
    const __half* __restrict__ Q, const __half* __restrict__ K,
    const __half* __restrict__ V, __half* __restrict__ O)
{
    __shared__ __align__(16) __half Ks[2][64][72];
    __shared__ __align__(16) __half Vs[2][64][72];

    const int tid = threadIdx.x;
    const int lane = tid & 31;
    const int wid = tid >> 5;
    const int qt = blockIdx.x;
    const int h = blockIdx.y;
    const int b = blockIdx.z;
    const int q0 = qt * 128 + wid * 16;
    const int g = lane >> 2;
    const int qd = lane & 3;
    const int l2 = lane & 15;

    const __half* Qb = Q + ((size_t)b * 2048 + q0) * GN + h * 64;
    const __half* Kb = K + (size_t)b * 4096 * GN + h * 64;
    const __half* Vb = V + (size_t)b * 4096 * GN + h * 64;

    // Q fragments (A operand), loaded once straight from gmem
    uint32_t qf[4][4];
#pragma unroll
    for (int ks = 0; ks < 4; ks++) {
        int c0 = ks * 16 + qd * 2;
        qf[ks][0] = *reinterpret_cast<const uint32_t*>(Qb + (size_t)g * GN + c0);
        qf[ks][1] = *reinterpret_cast<const uint32_t*>(Qb + (size_t)(g + 8) * GN + c0);
        qf[ks][2] = *reinterpret_cast<const uint32_t*>(Qb + (size_t)g * GN + c0 + 8);
        qf[ks][3] = *reinterpret_cast<const uint32_t*>(Qb + (size_t)(g + 8) * GN + c0 + 8);
    }

    float of[8][4];
#pragma unroll
    for (int i = 0; i < 8; i++)
#pragma unroll
        for (int j = 0; j < 4; j++) of[i][j] = 0.f;
    float m0 = -1e30f, m1 = -1e30f, l0 = 0.f, l1 = 0.f;

    const int lr = tid & 63;
    const int lc = (tid >> 6) * 16;

#define LOAD_KV(kb, s)                                                       \
    {                                                                        \
        const __half* Kg = Kb + (size_t)((kb) * 64 + lr) * GN + lc;          \
        const __half* Vg = Vb + (size_t)((kb) * 64 + lr) * GN + lc;          \
        cp16(smem_u32(&Ks[s][lr][lc]), Kg);                                  \
        cp16(smem_u32(&Ks[s][lr][lc + 8]), Kg + 8);                          \
        cp16(smem_u32(&Vs[s][lr][lc]), Vg);                                  \
        cp16(smem_u32(&Vs[s][lr][lc + 8]), Vg + 8);                          \
    }

    LOAD_KV(0, 0); cp_commit();

    for (int kb = 0; kb < 64; kb++) {
        const int s = kb & 1;
        if (kb < 63) {
            LOAD_KV(kb + 1, s ^ 1); cp_commit();
            cp_wait1();
        } else {
            cp_wait0();
        }
        __syncthreads();

        const uint32_t sK = smem_u32(&Ks[s][0][0]);
        const uint32_t sV = smem_u32(&Vs[s][0][0]);

        // S = Qs @ K^T : 8 key-tiles of 8, 4 d-steps of 16
        float sc[8][4];
#pragma unroll
        for (int nt = 0; nt < 8; nt++) {
            sc[nt][0] = 0.f; sc[nt][1] = 0.f; sc[nt][2] = 0.f; sc[nt][3] = 0.f;
#pragma unroll
            for (int ks = 0; ks < 4; ks++) {
                uint32_t bf[2];
                int row = nt * 8 + (l2 & 7);
                int col = ks * 16 + (l2 >> 3) * 8;
                ldsm_x2(bf, sK + (row * 72 + col) * 2);
                mma16816(sc[nt], qf[ks], bf);
            }
        }

        // online softmax (rows g and g+8; quad lanes share a row)
        float mx0 = -1e30f, mx1 = -1e30f;
#pragma unroll
        for (int nt = 0; nt < 8; nt++) {
            mx0 = fmaxf(mx0, fmaxf(sc[nt][0], sc[nt][1]));
            mx1 = fmaxf(mx1, fmaxf(sc[nt][2], sc[nt][3]));
        }
        mx0 = fmaxf(mx0, __shfl_xor_sync(0xffffffffu, mx0, 1));
        mx0 = fmaxf(mx0, __shfl_xor_sync(0xffffffffu, mx0, 2));
        mx1 = fmaxf(mx1, __shfl_xor_sync(0xffffffffu, mx1, 1));
        mx1 = fmaxf(mx1, __shfl_xor_sync(0xffffffffu, mx1, 2));
        float nm0 = fmaxf(m0, mx0);
        float nm1 = fmaxf(m1, mx1);
        float cr0 = exp2f(m0 - nm0);
        float cr1 = exp2f(m1 - nm1);
        float s0 = 0.f, s1 = 0.f;
#pragma unroll
        for (int nt = 0; nt < 8; nt++) {
            sc[nt][0] = exp2f(sc[nt][0] - nm0);
            sc[nt][1] = exp2f(sc[nt][1] - nm0);
            sc[nt][2] = exp2f(sc[nt][2] - nm1);
            sc[nt][3] = exp2f(sc[nt][3] - nm1);
            s0 += sc[nt][0] + sc[nt][1];
            s1 += sc[nt][2] + sc[nt][3];
        }
        s0 += __shfl_xor_sync(0xffffffffu, s0, 1);
        s0 += __shfl_xor_sync(0xffffffffu, s0, 2);
        s1 += __shfl_xor_sync(0xffffffffu, s1, 1);
        s1 += __shfl_xor_sync(0xffffffffu, s1, 2);
        l0 = l0 * cr0 + s0;
        l1 = l1 * cr1 + s1;
        m0 = nm0;
        m1 = nm1;
#pragma unroll
        for (int dn = 0; dn < 8; dn++) {
            of[dn][0] *= cr0; of[dn][1] *= cr0;
            of[dn][2] *= cr1; of[dn][3] *= cr1;
        }

        // pack P (fp16) into A-fragments for P@V
        uint32_t pf[4][4];
#pragma unroll
        for (int kp = 0; kp < 4; kp++) {
            pf[kp][0] = pack_h2(sc[2 * kp][0],     sc[2 * kp][1]);
            pf[kp][1] = pack_h2(sc[2 * kp][2],     sc[2 * kp][3]);
            pf[kp][2] = pack_h2(sc[2 * kp + 1][0], sc[2 * kp + 1][1]);
            pf[kp][3] = pack_h2(sc[2 * kp + 1][2], sc[2 * kp + 1][3]);
        }

        // O += P @ V : 8 d-tiles of 8, 4 key-steps of 16
#pragma unroll
        for (int dn = 0; dn < 8; dn++)
#pragma unroll
            for (int kp = 0; kp < 4; kp++) {
                uint32_t bf[2];
                ldsm_x2t(bf, sV + ((kp * 16 + l2) * 72 + dn * 8) * 2);
                mma16816(of[dn], pf[kp], bf);
            }
        __syncthreads();
    }

    // epilogue
    float inv0 = 1.f / l0;
    float inv1 = 1.f / l1;
    __half* Ob = O + ((size_t)b * 2048 + q0) * GN + h * 64;
#pragma unroll
    for (int dn = 0; dn < 8; dn++) {
        int col = dn * 8 + qd * 2;
        *reinterpret_cast<uint32_t*>(Ob + (size_t)g * GN + col) =
            pack_h2(of[dn][0] * inv0, of[dn][1] * inv0);
        *reinterpret_cast<uint32_t*>(Ob + (size_t)(g + 8) * GN + col) =
            pack_h2(of[dn][2] * inv1, of[dn][3] * inv1);
    }
}

// ---------------------------------------------------------------------------
extern "C" void kernel_launch(void* const* d_in, const int* in_sizes, int n_in,
                              void* d_out, int out_size)
{
    const float* x   = (const float*)d_in[0];
    const float* ctx = (const float*)d_in[1];
    const float* W0  = (const float*)d_in[2];   // Wq
    const float* b0  = (const float*)d_in[3];
    const float* W1  = (const float*)d_in[4];   // Wks
    const float* b1  = (const float*)d_in[5];
    const float* W2  = (const float*)d_in[6];   // Wvs
    const float* b2  = (const float*)d_in[7];
    const float* W3  = (const float*)d_in[8];   // Wkc
    const float* b3  = (const float*)d_in[9];
    const float* W4  = (const float*)d_in[10];  // Wvc
    const float* b4  = (const float*)d_in[11];
    const float* W5  = (const float*)d_in[12];  // Wo
    const float* b5  = (const float*)d_in[13];
    float* out = (float*)d_out;

    __half* xh;
    __half* ch;
    __half* Wt;
    __half* Qh;
    __half* Kh;
    __half* Vh;
    __half* Oh;
    cudaGetSymbolAddress((void**)&xh, g_xh);
    cudaGetSymbolAddress((void**)&ch, g_ch);
    cudaGetSymbolAddress((void**)&Wt, g_Wt);
    cudaGetSymbolAddress((void**)&Qh, g_Qh);
    cudaGetSymbolAddress((void**)&Kh, g_Kh);
    cudaGetSymbolAddress((void**)&Vh, g_Vh);
    cudaGetSymbolAddress((void**)&Oh, g_Oh);

    // fp32 -> fp16 inputs
    f2h_kernel<<<4096, 256>>>(x,   xh, 1048576);
    f2h_kernel<<<4096, 256>>>(ctx, ch, 1048576);

    // weights: transpose-convert to [N][K] fp16
    dim3 wgrid(32, 32);
    dim3 wblk(32, 8);
    wtrans_kernel<<<wgrid, wblk>>>(W0, Wt + 0u * 1048576u);
    wtrans_kernel<<<wgrid, wblk>>>(W1, Wt + 1u * 1048576u);
    wtrans_kernel<<<wgrid, wblk>>>(W2, Wt + 2u * 1048576u);
    wtrans_kernel<<<wgrid, wblk>>>(W3, Wt + 3u * 1048576u);
    wtrans_kernel<<<wgrid, wblk>>>(W4, Wt + 4u * 1048576u);
    wtrans_kernel<<<wgrid, wblk>>>(W5, Wt + 5u * 1048576u);

    cudaFuncSetAttribute(hgemm_kernel,
                         cudaFuncAttributeMaxDynamicSharedMemorySize, SM_GEMM);

    dim3 ggrid(8, 32);  // N/128, M/128
    const float qscale = 0.125f * 1.4426950408889634f;  // 1/sqrt(hd) * log2(e)

    // projections
    hgemm_kernel<<<ggrid, 256, SM_GEMM>>>(xh, Wt + 0u * 1048576u, b0, Qh, nullptr, 0, 2048, 0,    qscale);
    hgemm_kernel<<<ggrid, 256, SM_GEMM>>>(xh, Wt + 1u * 1048576u, b1, Kh, nullptr, 0, 4096, 0,    1.0f);
    hgemm_kernel<<<ggrid, 256, SM_GEMM>>>(ch, Wt + 3u * 1048576u, b3, Kh, nullptr, 0, 4096, 2048, 1.0f);
    hgemm_kernel<<<ggrid, 256, SM_GEMM>>>(xh, Wt + 2u * 1048576u, b2, Vh, nullptr, 0, 4096, 0,    1.0f);
    hgemm_kernel<<<ggrid, 256, SM_GEMM>>>(ch, Wt + 4u * 1048576u, b4, Vh, nullptr, 0, 4096, 2048, 1.0f);

    // attention
    dim3 agrid(16, 16, 2);
    attn_hmma_kernel<<<agrid, 256>>>(Qh, Kh, Vh, Oh);

    // output projection (fp32 out)
    hgemm_kernel<<<ggrid, 256, SM_GEMM>>>(Oh, Wt + 5u * 1048576u, b5, nullptr, out, 1, 2048, 0, 1.0f);
}

// round 6
// speedup vs baseline: 5.9556x; 1.0743x over previous
#include <cuda_runtime.h>
#include <cuda_fp16.h>
#include <stdint.h>
#include <math.h>

// Shapes: B=2, Tq=2048, Tctx=2048 -> Tk=4096, D=1024, H=16, hd=64
#define GK 1024
#define GN 1024

// ---------------- persistent fp16 scratch ----------------
__device__ __half g_xh[4194304];            // x fp16    [4096][1024]
__device__ __half g_ch[4194304];            // ctx fp16  [4096][1024]
__device__ __half g_Wt[6][1048576];         // W^T fp16  [1024 n][1024 k]
__device__ __half g_Qh[4194304];            // Q (scaled)[2*2048][1024]
__device__ __half g_Kh[8388608];            // K concat  [2*4096][1024]
__device__ __half g_Vh[8388608];            // V concat  [2*4096][1024]
__device__ __half g_Oh[4194304];            // attn out  [2*2048][1024]

// ---------------- ptx helpers ----------------
__device__ __forceinline__ uint32_t smem_u32(const void* p) {
    return static_cast<uint32_t>(__cvta_generic_to_shared(p));
}
__device__ __forceinline__ void cp16(uint32_t dst, const void* src) {
    asm volatile("cp.async.cg.shared.global [%0], [%1], 16;" :: "r"(dst), "l"(src));
}
__device__ __forceinline__ void cp_commit() {
    asm volatile("cp.async.commit_group;" ::: "memory");
}
__device__ __forceinline__ void cp_wait1() {
    asm volatile("cp.async.wait_group 1;" ::: "memory");
}
__device__ __forceinline__ void cp_wait0() {
    asm volatile("cp.async.wait_group 0;" ::: "memory");
}
__device__ __forceinline__ void ldsm_x4(uint32_t* r, uint32_t addr) {
    asm volatile("ldmatrix.sync.aligned.m8n8.x4.shared.b16 {%0,%1,%2,%3}, [%4];"
                 : "=r"(r[0]), "=r"(r[1]), "=r"(r[2]), "=r"(r[3]) : "r"(addr));
}
__device__ __forceinline__ void ldsm_x2(uint32_t* r, uint32_t addr) {
    asm volatile("ldmatrix.sync.aligned.m8n8.x2.shared.b16 {%0,%1}, [%2];"
                 : "=r"(r[0]), "=r"(r[1]) : "r"(addr));
}
__device__ __forceinline__ void ldsm_x2t(uint32_t* r, uint32_t addr) {
    asm volatile("ldmatrix.sync.aligned.m8n8.x2.trans.shared.b16 {%0,%1}, [%2];"
                 : "=r"(r[0]), "=r"(r[1]) : "r"(addr));
}
__device__ __forceinline__ void mma16816(float* c, const uint32_t* a, const uint32_t* b) {
    asm volatile(
        "mma.sync.aligned.m16n8k16.row.col.f32.f16.f16.f32 "
        "{%0,%1,%2,%3}, {%4,%5,%6,%7}, {%8,%9}, {%0,%1,%2,%3};"
        : "+f"(c[0]), "+f"(c[1]), "+f"(c[2]), "+f"(c[3])
        : "r"(a[0]), "r"(a[1]), "r"(a[2]), "r"(a[3]), "r"(b[0]), "r"(b[1]));
}
__device__ __forceinline__ uint32_t pack_h2(float lo, float hi) {
    __half2 h;
    h.x = __float2half_rn(lo);
    h.y = __float2half_rn(hi);
    uint32_t u;
    memcpy(&u, &h, 4);
    return u;
}
__device__ __forceinline__ uint32_t h2exp2(uint32_t x) {
    uint32_t r;
    asm volatile("ex2.approx.f16x2 %0, %1;" : "=r"(r) : "r"(x));
    return r;
}

// ---------------- fused fp32 -> fp16 convert (z selects tensor) ----------
__global__ void f2h2_kernel(const float* __restrict__ in0, const float* __restrict__ in1,
                            __half* __restrict__ out0, __half* __restrict__ out1, int n4) {
    const float* in = blockIdx.z ? in1 : in0;
    __half* out = blockIdx.z ? out1 : out0;
    int i = blockIdx.x * blockDim.x + threadIdx.x;
    if (i < n4) {
        float4 v = reinterpret_cast<const float4*>(in)[i];
        __half2 a; a.x = __float2half_rn(v.x); a.y = __float2half_rn(v.y);
        __half2 b; b.x = __float2half_rn(v.z); b.y = __float2half_rn(v.w);
        reinterpret_cast<__half2*>(out)[i * 2]     = a;
        reinterpret_cast<__half2*>(out)[i * 2 + 1] = b;
    }
}

// ---------------- fused W [K][N] fp32 -> Wt [N][K] fp16 (z = weight idx) ----
__global__ void wtrans6_kernel(const float* w0, const float* w1, const float* w2,
                               const float* w3, const float* w4, const float* w5,
                               __half* __restrict__ WtBase) {
    __shared__ float t[32][33];
    const float* W;
    switch (blockIdx.z) {
        case 0: W = w0; break;
        case 1: W = w1; break;
        case 2: W = w2; break;
        case 3: W = w3; break;
        case 4: W = w4; break;
        default: W = w5; break;
    }
    __half* Wt = WtBase + (size_t)blockIdx.z * 1048576u;
    int n0 = blockIdx.x * 32, k0 = blockIdx.y * 32;
    int tx = threadIdx.x, ty = threadIdx.y;
#pragma unroll
    for (int i = 0; i < 32; i += 8)
        t[ty + i][tx] = W[(size_t)(k0 + ty + i) * GN + n0 + tx];
    __syncthreads();
#pragma unroll
    for (int i = 0; i < 32; i += 8)
        Wt[(size_t)(n0 + ty + i) * GK + k0 + tx] = __float2half_rn(t[tx][ty + i]);
}

// ---------------- HMMA GEMM, 3-stage cp.async pipeline ----------------
// C[4096,1024] = A @ Wt^T + bias, x scale. 128x128 CTA tile, BK=32,
// 8 warps (2m x 4n), warp tile 64x32.
#define TSZ 10240
#define A_OFF(s) ((s) * TSZ)
#define B_OFF(s) (3 * TSZ + (s) * TSZ)
#define SM_GEMM (6 * TSZ)

struct GemmArgs {
    const __half* A;
    const __half* Bt;
    const float* bias;
    int roff;
};

__device__ __forceinline__ void hgemm_body(
    const __half* __restrict__ A, const __half* __restrict__ Bt,
    const float* __restrict__ bias, __half* __restrict__ outH,
    float* __restrict__ outF, int f32out, int bstride, int roff, float scale,
    char* smem)
{
    const uint32_t sb = smem_u32(smem);
    const int tid = threadIdx.x;
    const int lane = tid & 31;
    const int wid = tid >> 5;
    const int wm = (wid >> 2) * 64;
    const int wn = (wid & 3) * 32;
    const int row0 = blockIdx.y * 128;
    const int col0 = blockIdx.x * 128;

    const __half* Ag = A + (size_t)row0 * GK;
    const __half* Bg = Bt + (size_t)col0 * GK;

#define GLOAD(kc, s)                                                         \
    {                                                                        \
        _Pragma("unroll")                                                    \
        for (int j = 0; j < 2; j++) {                                        \
            int idx = tid + j * 256;                                         \
            int r = idx >> 2;                                                \
            int cb = (idx & 3) * 8;                                          \
            cp16(sb + A_OFF(s) + r * 80 + cb * 2,                            \
                 Ag + (size_t)r * GK + (kc) * 32 + cb);                      \
            cp16(sb + B_OFF(s) + r * 80 + cb * 2,                            \
                 Bg + (size_t)r * GK + (kc) * 32 + cb);                      \
        }                                                                    \
    }

    float acc[4][4][4];
#pragma unroll
    for (int i = 0; i < 4; i++)
#pragma unroll
        for (int j = 0; j < 4; j++)
#pragma unroll
            for (int k = 0; k < 4; k++) acc[i][j][k] = 0.f;

    GLOAD(0, 0); cp_commit();
    GLOAD(1, 1); cp_commit();

    for (int c = 0; c < 32; c++) {
        const int s = c % 3;
        cp_wait1();
        __syncthreads();
        if (c + 2 < 32) GLOAD(c + 2, (c + 2) % 3);
        cp_commit();

#pragma unroll
        for (int ks = 0; ks < 2; ks++) {
            uint32_t af[4][4];
#pragma unroll
            for (int mt = 0; mt < 4; mt++) {
                int row = wm + mt * 16 + (lane & 7) + (lane & 8);
                int col = ks * 16 + (lane >> 4) * 8;
                ldsm_x4(af[mt], sb + A_OFF(s) + (row * 40 + col) * 2);
            }
            uint32_t bf[4][2];
#pragma unroll
            for (int nt = 0; nt < 4; nt++) {
                int l2 = lane & 15;
                int row = wn + nt * 8 + (l2 & 7);
                int col = ks * 16 + (l2 >> 3) * 8;
                ldsm_x2(bf[nt], sb + B_OFF(s) + (row * 40 + col) * 2);
            }
#pragma unroll
            for (int mt = 0; mt < 4; mt++)
#pragma unroll
                for (int nt = 0; nt < 4; nt++)
                    mma16816(acc[mt][nt], af[mt], bf[nt]);
        }
    }

    const int g = lane >> 2;
    const int qd = lane & 3;
#pragma unroll
    for (int mt = 0; mt < 4; mt++) {
        int r0 = row0 + wm + mt * 16 + g;
        int r1 = r0 + 8;
        size_t or0 = (size_t)((r0 >> 11) * bstride + (r0 & 2047) + roff);
        size_t or1 = (size_t)((r1 >> 11) * bstride + (r1 & 2047) + roff);
#pragma unroll
        for (int nt = 0; nt < 4; nt++) {
            int col = col0 + wn + nt * 8 + qd * 2;
            float b0 = bias[col];
            float b1 = bias[col + 1];
            float v00 = (acc[mt][nt][0] + b0) * scale;
            float v01 = (acc[mt][nt][1] + b1) * scale;
            float v10 = (acc[mt][nt][2] + b0) * scale;
            float v11 = (acc[mt][nt][3] + b1) * scale;
            if (f32out) {
                outF[or0 * GN + col]     = v00;
                outF[or0 * GN + col + 1] = v01;
                outF[or1 * GN + col]     = v10;
                outF[or1 * GN + col + 1] = v11;
            } else {
                *reinterpret_cast<uint32_t*>(&outH[or0 * GN + col]) = pack_h2(v00, v01);
                *reinterpret_cast<uint32_t*>(&outH[or1 * GN + col]) = pack_h2(v10, v11);
            }
        }
    }
}

__global__ __launch_bounds__(256) void hgemm_kernel(
    const __half* __restrict__ A, const __half* __restrict__ Bt,
    const float* __restrict__ bias, __half* __restrict__ outH,
    float* __restrict__ outF, int f32out, int bstride, int roff, float scale)
{
    extern __shared__ char smem[];
    hgemm_body(A, Bt, bias, outH, outF, f32out, bstride, roff, scale, smem);
}

// fused dual-source GEMM (blockIdx.z selects {A, W, bias, roff}); fp16 out,
// bstride 4096 (concat K/V buffers)
__global__ __launch_bounds__(256) void hgemm2_kernel(
    const __half* __restrict__ A0, const __half* __restrict__ A1,
    const __half* __restrict__ Bt0, const __half* __restrict__ Bt1,
    const float* __restrict__ bias0, const float* __restrict__ bias1,
    __half* __restrict__ outH)
{
    extern __shared__ char smem[];
    if (blockIdx.z == 0)
        hgemm_body(A0, Bt0, bias0, outH, nullptr, 0, 4096, 0, 1.0f, smem);
    else
        hgemm_body(A1, Bt1, bias1, outH, nullptr, 0, 4096, 2048, 1.0f, smem);
}

// ---------------- flash attention (HMMA, cp.async double-buffered K/V) ------
// fp16x2 exp + ones-MMA row sums.
__global__ __launch_bounds__(256) void attn_hmma_kernel(
    const __half* __restrict__ Q, const __half* __restrict__ K,
    const __half* __restrict__ V, __half* __restrict__ O)
{
    __shared__ __align__(16) __half Ks[2][64][72];
    __shared__ __align__(16) __half Vs[2][64][72];

    const int tid = threadIdx.x;
    const int lane = tid & 31;
    const int wid = tid >> 5;
    const int qt = blockIdx.x;
    const int h = blockIdx.y;
    const int b = blockIdx.z;
    const int q0 = qt * 128 + wid * 16;
    const int g = lane >> 2;
    const int qd = lane & 3;
    const int l2 = lane & 15;

    const __half* Qb = Q + ((size_t)b * 2048 + q0) * GN + h * 64;
    const __half* Kb = K + (size_t)b * 4096 * GN + h * 64;
    const __half* Vb = V + (size_t)b * 4096 * GN + h * 64;

    // Q fragments (A operand)
    uint32_t qf[4][4];
#pragma unroll
    for (int ks = 0; ks < 4; ks++) {
        int c0 = ks * 16 + qd * 2;
        qf[ks][0] = *reinterpret_cast<const uint32_t*>(Qb + (size_t)g * GN + c0);
        qf[ks][1] = *reinterpret_cast<const uint32_t*>(Qb + (size_t)(g + 8) * GN + c0);
        qf[ks][2] = *reinterpret_cast<const uint32_t*>(Qb + (size_t)g * GN + c0 + 8);
        qf[ks][3] = *reinterpret_cast<const uint32_t*>(Qb + (size_t)(g + 8) * GN + c0 + 8);
    }

    float of[8][4];
#pragma unroll
    for (int i = 0; i < 8; i++)
#pragma unroll
        for (int j = 0; j < 4; j++) of[i][j] = 0.f;
    float ls[4] = {0.f, 0.f, 0.f, 0.f};   // row sums (cols duplicated)
    float m0 = -1e30f, m1 = -1e30f;

    const uint32_t ONES2 = 0x3C003C00u;    // half2(1,1)
    const uint32_t onesb[2] = {ONES2, ONES2};

    const int lr = tid & 63;
    const int lc = (tid >> 6) * 16;

#define LOAD_KV(kb, s)                                                       \
    {                                                                        \
        const __half* Kg = Kb + (size_t)((kb) * 64 + lr) * GN + lc;          \
        const __half* Vg = Vb + (size_t)((kb) * 64 + lr) * GN + lc;          \
        cp16(smem_u32(&Ks[s][lr][lc]), Kg);                                  \
        cp16(smem_u32(&Ks[s][lr][lc + 8]), Kg + 8);                          \
        cp16(smem_u32(&Vs[s][lr][lc]), Vg);                                  \
        cp16(smem_u32(&Vs[s][lr][lc + 8]), Vg + 8);                          \
    }

    LOAD_KV(0, 0); cp_commit();

    for (int kb = 0; kb < 64; kb++) {
        const int s = kb & 1;
        if (kb < 63) {
            LOAD_KV(kb + 1, s ^ 1); cp_commit();
            cp_wait1();
        } else {
            cp_wait0();
        }
        __syncthreads();

        const uint32_t sK = smem_u32(&Ks[s][0][0]);
        const uint32_t sV = smem_u32(&Vs[s][0][0]);

        // S = Qs @ K^T
        float sc[8][4];
#pragma unroll
        for (int nt = 0; nt < 8; nt++) {
            sc[nt][0] = 0.f; sc[nt][1] = 0.f; sc[nt][2] = 0.f; sc[nt][3] = 0.f;
#pragma unroll
            for (int ks = 0; ks < 4; ks++) {
                uint32_t bf[2];
                int row = nt * 8 + (l2 & 7);
                int col = ks * 16 + (l2 >> 3) * 8;
                ldsm_x2(bf, sK + (row * 72 + col) * 2);
                mma16816(sc[nt], qf[ks], bf);
            }
        }

        // online softmax: max reduce (quad lanes share rows g, g+8)
        float mx0 = -1e30f, mx1 = -1e30f;
#pragma unroll
        for (int nt = 0; nt < 8; nt++) {
            mx0 = fmaxf(mx0, fmaxf(sc[nt][0], sc[nt][1]));
            mx1 = fmaxf(mx1, fmaxf(sc[nt][2], sc[nt][3]));
        }
        mx0 = fmaxf(mx0, __shfl_xor_sync(0xffffffffu, mx0, 1));
        mx0 = fmaxf(mx0, __shfl_xor_sync(0xffffffffu, mx0, 2));
        mx1 = fmaxf(mx1, __shfl_xor_sync(0xffffffffu, mx1, 1));
        mx1 = fmaxf(mx1, __shfl_xor_sync(0xffffffffu, mx1, 2));
        float nm0 = fmaxf(m0, mx0);
        float nm1 = fmaxf(m1, mx1);
        float cr0 = exp2f(m0 - nm0);
        float cr1 = exp2f(m1 - nm1);
        m0 = nm0;
        m1 = nm1;

        // rescale accumulators
        ls[0] *= cr0; ls[1] *= cr0; ls[2] *= cr1; ls[3] *= cr1;
#pragma unroll
        for (int dn = 0; dn < 8; dn++) {
            of[dn][0] *= cr0; of[dn][1] *= cr0;
            of[dn][2] *= cr1; of[dn][3] *= cr1;
        }

        // P = exp2(S - m) computed directly in fp16x2 (A-fragment layout)
        uint32_t pf[4][4];
#pragma unroll
        for (int kp = 0; kp < 4; kp++) {
            pf[kp][0] = h2exp2(pack_h2(sc[2 * kp][0] - nm0,     sc[2 * kp][1] - nm0));
            pf[kp][1] = h2exp2(pack_h2(sc[2 * kp][2] - nm1,     sc[2 * kp][3] - nm1));
            pf[kp][2] = h2exp2(pack_h2(sc[2 * kp + 1][0] - nm0, sc[2 * kp + 1][1] - nm0));
            pf[kp][3] = h2exp2(pack_h2(sc[2 * kp + 1][2] - nm1, sc[2 * kp + 1][3] - nm1));
        }

        // row sums via ones-MMA (exact fp32 cross-lane reduction)
#pragma unroll
        for (int kp = 0; kp < 4; kp++)
            mma16816(ls, pf[kp], onesb);

        // O += P @ V
#pragma unroll
        for (int dn = 0; dn < 8; dn++)
#pragma unroll
            for (int kp = 0; kp < 4; kp++) {
                uint32_t bf[2];
                ldsm_x2t(bf, sV + ((kp * 16 + l2) * 72 + dn * 8) * 2);
                mma16816(of[dn], pf[kp], bf);
            }
        __syncthreads();
    }

    // epilogue
    float inv0 = 1.f / ls[0];
    float inv1 = 1.f / ls[2];
    __half* Ob = O + ((size_t)b * 2048 + q0) * GN + h * 64;
#pragma unroll
    for (int dn = 0; dn < 8; dn++) {
        int col = dn * 8 + qd * 2;
        *reinterpret_cast<uint32_t*>(Ob + (size_t)g * GN + col) =
            pack_h2(of[dn][0] * inv0, of[dn][1] * inv0);
        *reinterpret_cast<uint32_t*>(Ob + (size_t)(g + 8) * GN + col) =
            pack_h2(of[dn][2] * inv1, of[dn][3] * inv1);
    }
}

// ---------------------------------------------------------------------------
extern "C" void kernel_launch(void* const* d_in, const int* in_sizes, int n_in,
                              void* d_out, int out_size)
{
    const float* x   = (const float*)d_in[0];
    const float* ctx = (const float*)d_in[1];
    const float* W0  = (const float*)d_in[2];   // Wq
    const float* b0  = (const float*)d_in[3];
    const float* W1  = (const float*)d_in[4];   // Wks
    const float* b1  = (const float*)d_in[5];
    const float* W2  = (const float*)d_in[6];   // Wvs
    const float* b2  = (const float*)d_in[7];
    const float* W3  = (const float*)d_in[8];   // Wkc
    const float* b3  = (const float*)d_in[9];
    const float* W4  = (const float*)d_in[10];  // Wvc
    const float* b4  = (const float*)d_in[11];
    const float* W5  = (const float*)d_in[12];  // Wo
    const float* b5  = (const float*)d_in[13];
    float* out = (float*)d_out;

    __half* xh;
    __half* ch;
    __half* Wt;
    __half* Qh;
    __half* Kh;
    __half* Vh;
    __half* Oh;
    cudaGetSymbolAddress((void**)&xh, g_xh);
    cudaGetSymbolAddress((void**)&ch, g_ch);
    cudaGetSymbolAddress((void**)&Wt, g_Wt);
    cudaGetSymbolAddress((void**)&Qh, g_Qh);
    cudaGetSymbolAddress((void**)&Kh, g_Kh);
    cudaGetSymbolAddress((void**)&Vh, g_Vh);
    cudaGetSymbolAddress((void**)&Oh, g_Oh);

    // launch 0: fp32 -> fp16 inputs (fused)
    dim3 fgrid(4096, 1, 2);
    f2h2_kernel<<<fgrid, 256>>>(x, ctx, xh, ch, 1048576);

    // launch 1: weights transpose-convert (fused, z = weight idx)
    dim3 wgrid(32, 32, 6);
    dim3 wblk(32, 8);
    wtrans6_kernel<<<wgrid, wblk>>>(W0, W1, W2, W3, W4, W5, Wt);

    cudaFuncSetAttribute(hgemm_kernel,
                         cudaFuncAttributeMaxDynamicSharedMemorySize, SM_GEMM);
    cudaFuncSetAttribute(hgemm2_kernel,
                         cudaFuncAttributeMaxDynamicSharedMemorySize, SM_GEMM);

    dim3 ggrid(8, 32);      // N/128, M/128
    dim3 ggrid2(8, 32, 2);
    const float qscale = 0.125f * 1.4426950408889634f;  // 1/sqrt(hd) * log2(e)

    // launch 2: Q projection
    hgemm_kernel<<<ggrid, 256, SM_GEMM>>>(xh, Wt + 0u * 1048576u, b0, Qh, nullptr, 0, 2048, 0, qscale);
    // launch 3: K projection (self + context fused)
    hgemm2_kernel<<<ggrid2, 256, SM_GEMM>>>(xh, ch, Wt + 1u * 1048576u, Wt + 3u * 1048576u, b1, b3, Kh);
    // launch 4: V projection (self + context fused)
    hgemm2_kernel<<<ggrid2, 256, SM_GEMM>>>(xh, ch, Wt + 2u * 1048576u, Wt + 4u * 1048576u, b2, b4, Vh);

    // launch 5: attention (lands at ncu capture index)
    dim3 agrid(16, 16, 2);
    attn_hmma_kernel<<<agrid, 256>>>(Qh, Kh, Vh, Oh);

    // launch 6: output projection (fp32 out)
    hgemm_kernel<<<ggrid, 256, SM_GEMM>>>(Oh, Wt + 5u * 1048576u, b5, nullptr, out, 1, 2048, 0, 1.0f);
}

// round 7
// speedup vs baseline: 6.1402x; 1.0310x over previous
#include <cuda_runtime.h>
#include <cuda_fp16.h>
#include <stdint.h>
#include <math.h>

// Shapes: B=2, Tq=2048, Tctx=2048 -> Tk=4096, D=1024, H=16, hd=64
#define GK 1024
#define GN 1024

// ---------------- persistent fp16 scratch ----------------
__device__ __half g_xh[4194304];            // x fp16    [4096][1024]
__device__ __half g_ch[4194304];            // ctx fp16  [4096][1024]
__device__ __half g_Wt[6][1048576];         // W^T fp16  [1024 n][1024 k]
__device__ __half g_Qh[4194304];            // Q (scaled)[2*2048][1024]
__device__ __half g_Kh[8388608];            // K concat  [2*4096][1024]
__device__ __half g_Vh[8388608];            // V concat  [2*4096][1024]
__device__ __half g_Oh[4194304];            // attn out  [2*2048][1024]

// ---------------- ptx helpers ----------------
__device__ __forceinline__ uint32_t smem_u32(const void* p) {
    return static_cast<uint32_t>(__cvta_generic_to_shared(p));
}
__device__ __forceinline__ void cp16(uint32_t dst, const void* src) {
    asm volatile("cp.async.cg.shared.global [%0], [%1], 16;" :: "r"(dst), "l"(src));
}
__device__ __forceinline__ void cp_commit() {
    asm volatile("cp.async.commit_group;" ::: "memory");
}
__device__ __forceinline__ void cp_wait1() {
    asm volatile("cp.async.wait_group 1;" ::: "memory");
}
__device__ __forceinline__ void ldsm_x4(uint32_t* r, uint32_t addr) {
    asm volatile("ldmatrix.sync.aligned.m8n8.x4.shared.b16 {%0,%1,%2,%3}, [%4];"
                 : "=r"(r[0]), "=r"(r[1]), "=r"(r[2]), "=r"(r[3]) : "r"(addr));
}
__device__ __forceinline__ void ldsm_x2(uint32_t* r, uint32_t addr) {
    asm volatile("ldmatrix.sync.aligned.m8n8.x2.shared.b16 {%0,%1}, [%2];"
                 : "=r"(r[0]), "=r"(r[1]) : "r"(addr));
}
__device__ __forceinline__ void ldsm_x2t(uint32_t* r, uint32_t addr) {
    asm volatile("ldmatrix.sync.aligned.m8n8.x2.trans.shared.b16 {%0,%1}, [%2];"
                 : "=r"(r[0]), "=r"(r[1]) : "r"(addr));
}
__device__ __forceinline__ void mma16816(float* c, const uint32_t* a, const uint32_t* b) {
    asm volatile(
        "mma.sync.aligned.m16n8k16.row.col.f32.f16.f16.f32 "
        "{%0,%1,%2,%3}, {%4,%5,%6,%7}, {%8,%9}, {%0,%1,%2,%3};"
        : "+f"(c[0]), "+f"(c[1]), "+f"(c[2]), "+f"(c[3])
        : "r"(a[0]), "r"(a[1]), "r"(a[2]), "r"(a[3]), "r"(b[0]), "r"(b[1]));
}
__device__ __forceinline__ uint32_t pack_h2(float lo, float hi) {
    __half2 h;
    h.x = __float2half_rn(lo);
    h.y = __float2half_rn(hi);
    uint32_t u;
    memcpy(&u, &h, 4);
    return u;
}
__device__ __forceinline__ uint32_t h2exp2(uint32_t x) {
    uint32_t r;
    asm volatile("ex2.approx.f16x2 %0, %1;" : "=r"(r) : "r"(x));
    return r;
}

// ---------------- fused fp32 -> fp16 convert (z selects tensor) ----------
__global__ void f2h2_kernel(const float* __restrict__ in0, const float* __restrict__ in1,
                            __half* __restrict__ out0, __half* __restrict__ out1, int n4) {
    const float* in = blockIdx.z ? in1 : in0;
    __half* out = blockIdx.z ? out1 : out0;
    int i = blockIdx.x * blockDim.x + threadIdx.x;
    if (i < n4) {
        float4 v = reinterpret_cast<const float4*>(in)[i];
        __half2 a; a.x = __float2half_rn(v.x); a.y = __float2half_rn(v.y);
        __half2 b; b.x = __float2half_rn(v.z); b.y = __float2half_rn(v.w);
        reinterpret_cast<__half2*>(out)[i * 2]     = a;
        reinterpret_cast<__half2*>(out)[i * 2 + 1] = b;
    }
}

// ---------------- fused W [K][N] fp32 -> Wt [N][K] fp16 (z = weight idx) ----
__global__ void wtrans6_kernel(const float* w0, const float* w1, const float* w2,
                               const float* w3, const float* w4, const float* w5,
                               __half* __restrict__ WtBase) {
    __shared__ float t[32][33];
    const float* W;
    switch (blockIdx.z) {
        case 0: W = w0; break;
        case 1: W = w1; break;
        case 2: W = w2; break;
        case 3: W = w3; break;
        case 4: W = w4; break;
        default: W = w5; break;
    }
    __half* Wt = WtBase + (size_t)blockIdx.z * 1048576u;
    int n0 = blockIdx.x * 32, k0 = blockIdx.y * 32;
    int tx = threadIdx.x, ty = threadIdx.y;
#pragma unroll
    for (int i = 0; i < 32; i += 8)
        t[ty + i][tx] = W[(size_t)(k0 + ty + i) * GN + n0 + tx];
    __syncthreads();
#pragma unroll
    for (int i = 0; i < 32; i += 8)
        Wt[(size_t)(n0 + ty + i) * GK + k0 + tx] = __float2half_rn(t[tx][ty + i]);
}

// ---------------- HMMA GEMM, 3-stage cp.async pipeline ----------------
#define TSZ 10240
#define A_OFF(s) ((s) * TSZ)
#define B_OFF(s) (3 * TSZ + (s) * TSZ)
#define SM_GEMM (6 * TSZ)

__device__ __forceinline__ void hgemm_body(
    const __half* __restrict__ A, const __half* __restrict__ Bt,
    const float* __restrict__ bias, __half* __restrict__ outH,
    float* __restrict__ outF, int f32out, int bstride, int roff, float scale,
    char* smem)
{
    const uint32_t sb = smem_u32(smem);
    const int tid = threadIdx.x;
    const int lane = tid & 31;
    const int wid = tid >> 5;
    const int wm = (wid >> 2) * 64;
    const int wn = (wid & 3) * 32;
    const int row0 = blockIdx.y * 128;
    const int col0 = blockIdx.x * 128;

    const __half* Ag = A + (size_t)row0 * GK;
    const __half* Bg = Bt + (size_t)col0 * GK;

#define GLOAD(kc, s)                                                         \
    {                                                                        \
        _Pragma("unroll")                                                    \
        for (int j = 0; j < 2; j++) {                                        \
            int idx = tid + j * 256;                                         \
            int r = idx >> 2;                                                \
            int cb = (idx & 3) * 8;                                          \
            cp16(sb + A_OFF(s) + r * 80 + cb * 2,                            \
                 Ag + (size_t)r * GK + (kc) * 32 + cb);                      \
            cp16(sb + B_OFF(s) + r * 80 + cb * 2,                            \
                 Bg + (size_t)r * GK + (kc) * 32 + cb);                      \
        }                                                                    \
    }

    float acc[4][4][4];
#pragma unroll
    for (int i = 0; i < 4; i++)
#pragma unroll
        for (int j = 0; j < 4; j++)
#pragma unroll
            for (int k = 0; k < 4; k++) acc[i][j][k] = 0.f;

    GLOAD(0, 0); cp_commit();
    GLOAD(1, 1); cp_commit();

    for (int c = 0; c < 32; c++) {
        const int s = c % 3;
        cp_wait1();
        __syncthreads();
        if (c + 2 < 32) GLOAD(c + 2, (c + 2) % 3);
        cp_commit();

#pragma unroll
        for (int ks = 0; ks < 2; ks++) {
            uint32_t af[4][4];
#pragma unroll
            for (int mt = 0; mt < 4; mt++) {
                int row = wm + mt * 16 + (lane & 7) + (lane & 8);
                int col = ks * 16 + (lane >> 4) * 8;
                ldsm_x4(af[mt], sb + A_OFF(s) + (row * 40 + col) * 2);
            }
            uint32_t bf[4][2];
#pragma unroll
            for (int nt = 0; nt < 4; nt++) {
                int l2 = lane & 15;
                int row = wn + nt * 8 + (l2 & 7);
                int col = ks * 16 + (l2 >> 3) * 8;
                ldsm_x2(bf[nt], sb + B_OFF(s) + (row * 40 + col) * 2);
            }
#pragma unroll
            for (int mt = 0; mt < 4; mt++)
#pragma unroll
                for (int nt = 0; nt < 4; nt++)
                    mma16816(acc[mt][nt], af[mt], bf[nt]);
        }
    }

    const int g = lane >> 2;
    const int qd = lane & 3;
#pragma unroll
    for (int mt = 0; mt < 4; mt++) {
        int r0 = row0 + wm + mt * 16 + g;
        int r1 = r0 + 8;
        size_t or0 = (size_t)((r0 >> 11) * bstride + (r0 & 2047) + roff);
        size_t or1 = (size_t)((r1 >> 11) * bstride + (r1 & 2047) + roff);
#pragma unroll
        for (int nt = 0; nt < 4; nt++) {
            int col = col0 + wn + nt * 8 + qd * 2;
            float b0 = bias[col];
            float b1 = bias[col + 1];
            float v00 = (acc[mt][nt][0] + b0) * scale;
            float v01 = (acc[mt][nt][1] + b1) * scale;
            float v10 = (acc[mt][nt][2] + b0) * scale;
            float v11 = (acc[mt][nt][3] + b1) * scale;
            if (f32out) {
                outF[or0 * GN + col]     = v00;
                outF[or0 * GN + col + 1] = v01;
                outF[or1 * GN + col]     = v10;
                outF[or1 * GN + col + 1] = v11;
            } else {
                *reinterpret_cast<uint32_t*>(&outH[or0 * GN + col]) = pack_h2(v00, v01);
                *reinterpret_cast<uint32_t*>(&outH[or1 * GN + col]) = pack_h2(v10, v11);
            }
        }
    }
}

__global__ __launch_bounds__(256) void hgemm_kernel(
    const __half* __restrict__ A, const __half* __restrict__ Bt,
    const float* __restrict__ bias, __half* __restrict__ outH,
    float* __restrict__ outF, int f32out, int bstride, int roff, float scale)
{
    extern __shared__ char smem[];
    hgemm_body(A, Bt, bias, outH, outF, f32out, bstride, roff, scale, smem);
}

__global__ __launch_bounds__(256) void hgemm2_kernel(
    const __half* __restrict__ A0, const __half* __restrict__ A1,
    const __half* __restrict__ Bt0, const __half* __restrict__ Bt1,
    const float* __restrict__ bias0, const float* __restrict__ bias1,
    __half* __restrict__ outH)
{
    extern __shared__ char smem[];
    if (blockIdx.z == 0)
        hgemm_body(A0, Bt0, bias0, outH, nullptr, 0, 4096, 0, 1.0f, smem);
    else
        hgemm_body(A1, Bt1, bias1, outH, nullptr, 0, 4096, 2048, 1.0f, smem);
}

// ---------------- flash attention (HMMA) ----------------
// 3-stage cp.async K/V ring (prefetch depth 2, ONE barrier per iteration),
// hoisted ldsm batches, fp16x2 exp, ones-MMA row sums.
// Dynamic smem: stage s at KOFF/VOFF, 64x72 halves each.
#define KVSTG 18432                       // (64*72*2) * 2 tensors
#define KOFF(s) ((s) * KVSTG)
#define VOFF(s) ((s) * KVSTG + 9216)
#define SM_ATTN (3 * KVSTG)               // 55296 B

__global__ __launch_bounds__(256) void attn_hmma_kernel(
    const __half* __restrict__ Q, const __half* __restrict__ K,
    const __half* __restrict__ V, __half* __restrict__ O)
{
    extern __shared__ char smem[];
    const uint32_t sb = smem_u32(smem);

    const int tid = threadIdx.x;
    const int lane = tid & 31;
    const int wid = tid >> 5;
    const int qt = blockIdx.x;
    const int h = blockIdx.y;
    const int b = blockIdx.z;
    const int q0 = qt * 128 + wid * 16;
    const int g = lane >> 2;
    const int qd = lane & 3;
    const int l2 = lane & 15;

    const __half* Qb = Q + ((size_t)b * 2048 + q0) * GN + h * 64;
    const __half* Kb = K + (size_t)b * 4096 * GN + h * 64;
    const __half* Vb = V + (size_t)b * 4096 * GN + h * 64;

    // Q fragments (A operand)
    uint32_t qf[4][4];
#pragma unroll
    for (int ks = 0; ks < 4; ks++) {
        int c0 = ks * 16 + qd * 2;
        qf[ks][0] = *reinterpret_cast<const uint32_t*>(Qb + (size_t)g * GN + c0);
        qf[ks][1] = *reinterpret_cast<const uint32_t*>(Qb + (size_t)(g + 8) * GN + c0);
        qf[ks][2] = *reinterpret_cast<const uint32_t*>(Qb + (size_t)g * GN + c0 + 8);
        qf[ks][3] = *reinterpret_cast<const uint32_t*>(Qb + (size_t)(g + 8) * GN + c0 + 8);
    }

    float of[8][4];
#pragma unroll
    for (int i = 0; i < 8; i++)
#pragma unroll
        for (int j = 0; j < 4; j++) of[i][j] = 0.f;
    float ls[4] = {0.f, 0.f, 0.f, 0.f};
    float m0 = -1e30f, m1 = -1e30f;

    const uint32_t ONES2 = 0x3C003C00u;
    const uint32_t onesb[2] = {ONES2, ONES2};

    const int lr = tid & 63;
    const int lc = (tid >> 6) * 16;

#define LOAD_KV(kb, s)                                                       \
    {                                                                        \
        const __half* Kg = Kb + (size_t)((kb) * 64 + lr) * GN + lc;          \
        const __half* Vg = Vb + (size_t)((kb) * 64 + lr) * GN + lc;          \
        cp16(sb + KOFF(s) + (lr * 72 + lc) * 2, Kg);                         \
        cp16(sb + KOFF(s) + (lr * 72 + lc + 8) * 2, Kg + 8);                 \
        cp16(sb + VOFF(s) + (lr * 72 + lc) * 2, Vg);                         \
        cp16(sb + VOFF(s) + (lr * 72 + lc + 8) * 2, Vg + 8);                 \
    }

    LOAD_KV(0, 0); cp_commit();
    LOAD_KV(1, 1); cp_commit();

    for (int kb = 0; kb < 64; kb++) {
        const int s = kb % 3;
        cp_wait1();           // group kb complete (1 group committed per iter)
        __syncthreads();      // data visible + stage (kb+2)%3 reads (iter kb-1) done
        if (kb + 2 < 64) LOAD_KV(kb + 2, (kb + 2) % 3);
        cp_commit();

        const uint32_t sK = sb + KOFF(s);
        const uint32_t sV = sb + VOFF(s);

        // S = Qs @ K^T : hoisted ldsm per d-step
        float sc[8][4];
#pragma unroll
        for (int nt = 0; nt < 8; nt++) {
            sc[nt][0] = 0.f; sc[nt][1] = 0.f; sc[nt][2] = 0.f; sc[nt][3] = 0.f;
        }
#pragma unroll
        for (int ks = 0; ks < 4; ks++) {
            uint32_t bf[8][2];
            int col = ks * 16 + (l2 >> 3) * 8;
#pragma unroll
            for (int nt = 0; nt < 8; nt++)
                ldsm_x2(bf[nt], sK + ((nt * 8 + (l2 & 7)) * 72 + col) * 2);
#pragma unroll
            for (int nt = 0; nt < 8; nt++)
                mma16816(sc[nt], qf[ks], bf[nt]);
        }

        // online softmax max-reduce
        float mx0 = -1e30f, mx1 = -1e30f;
#pragma unroll
        for (int nt = 0; nt < 8; nt++) {
            mx0 = fmaxf(mx0, fmaxf(sc[nt][0], sc[nt][1]));
            mx1 = fmaxf(mx1, fmaxf(sc[nt][2], sc[nt][3]));
        }
        mx0 = fmaxf(mx0, __shfl_xor_sync(0xffffffffu, mx0, 1));
        mx0 = fmaxf(mx0, __shfl_xor_sync(0xffffffffu, mx0, 2));
        mx1 = fmaxf(mx1, __shfl_xor_sync(0xffffffffu, mx1, 1));
        mx1 = fmaxf(mx1, __shfl_xor_sync(0xffffffffu, mx1, 2));
        float nm0 = fmaxf(m0, mx0);
        float nm1 = fmaxf(m1, mx1);
        float cr0 = exp2f(m0 - nm0);
        float cr1 = exp2f(m1 - nm1);
        m0 = nm0;
        m1 = nm1;

        ls[0] *= cr0; ls[1] *= cr0; ls[2] *= cr1; ls[3] *= cr1;
#pragma unroll
        for (int dn = 0; dn < 8; dn++) {
            of[dn][0] *= cr0; of[dn][1] *= cr0;
            of[dn][2] *= cr1; of[dn][3] *= cr1;
        }

        // P = exp2(S - m) in fp16x2 (A-fragment layout)
        uint32_t pf[4][4];
#pragma unroll
        for (int kp = 0; kp < 4; kp++) {
            pf[kp][0] = h2exp2(pack_h2(sc[2 * kp][0] - nm0,     sc[2 * kp][1] - nm0));
            pf[kp][1] = h2exp2(pack_h2(sc[2 * kp][2] - nm1,     sc[2 * kp][3] - nm1));
            pf[kp][2] = h2exp2(pack_h2(sc[2 * kp + 1][0] - nm0, sc[2 * kp + 1][1] - nm0));
            pf[kp][3] = h2exp2(pack_h2(sc[2 * kp + 1][2] - nm1, sc[2 * kp + 1][3] - nm1));
        }

        // row sums via ones-MMA
#pragma unroll
        for (int kp = 0; kp < 4; kp++)
            mma16816(ls, pf[kp], onesb);

        // O += P @ V : hoisted ldsm per key-step
#pragma unroll
        for (int kp = 0; kp < 4; kp++) {
            uint32_t vf[8][2];
#pragma unroll
            for (int dn = 0; dn < 8; dn++)
                ldsm_x2t(vf[dn], sV + ((kp * 16 + l2) * 72 + dn * 8) * 2);
#pragma unroll
            for (int dn = 0; dn < 8; dn++)
                mma16816(of[dn], pf[kp], vf[dn]);
        }
    }

    // epilogue
    float inv0 = 1.f / ls[0];
    float inv1 = 1.f / ls[2];
    __half* Ob = O + ((size_t)b * 2048 + q0) * GN + h * 64;
#pragma unroll
    for (int dn = 0; dn < 8; dn++) {
        int col = dn * 8 + qd * 2;
        *reinterpret_cast<uint32_t*>(Ob + (size_t)g * GN + col) =
            pack_h2(of[dn][0] * inv0, of[dn][1] * inv0);
        *reinterpret_cast<uint32_t*>(Ob + (size_t)(g + 8) * GN + col) =
            pack_h2(of[dn][2] * inv1, of[dn][3] * inv1);
    }
}

// ---------------------------------------------------------------------------
extern "C" void kernel_launch(void* const* d_in, const int* in_sizes, int n_in,
                              void* d_out, int out_size)
{
    const float* x   = (const float*)d_in[0];
    const float* ctx = (const float*)d_in[1];
    const float* W0  = (const float*)d_in[2];   // Wq
    const float* b0  = (const float*)d_in[3];
    const float* W1  = (const float*)d_in[4];   // Wks
    const float* b1  = (const float*)d_in[5];
    const float* W2  = (const float*)d_in[6];   // Wvs
    const float* b2  = (const float*)d_in[7];
    const float* W3  = (const float*)d_in[8];   // Wkc
    const float* b3  = (const float*)d_in[9];
    const float* W4  = (const float*)d_in[10];  // Wvc
    const float* b4  = (const float*)d_in[11];
    const float* W5  = (const float*)d_in[12];  // Wo
    const float* b5  = (const float*)d_in[13];
    float* out = (float*)d_out;

    __half* xh;
    __half* ch;
    __half* Wt;
    __half* Qh;
    __half* Kh;
    __half* Vh;
    __half* Oh;
    cudaGetSymbolAddress((void**)&xh, g_xh);
    cudaGetSymbolAddress((void**)&ch, g_ch);
    cudaGetSymbolAddress((void**)&Wt, g_Wt);
    cudaGetSymbolAddress((void**)&Qh, g_Qh);
    cudaGetSymbolAddress((void**)&Kh, g_Kh);
    cudaGetSymbolAddress((void**)&Vh, g_Vh);
    cudaGetSymbolAddress((void**)&Oh, g_Oh);

    // launch 0: fp32 -> fp16 inputs (fused)
    dim3 fgrid(4096, 1, 2);
    f2h2_kernel<<<fgrid, 256>>>(x, ctx, xh, ch, 1048576);

    // launch 1: weights transpose-convert (fused)
    dim3 wgrid(32, 32, 6);
    dim3 wblk(32, 8);
    wtrans6_kernel<<<wgrid, wblk>>>(W0, W1, W2, W3, W4, W5, Wt);

    cudaFuncSetAttribute(hgemm_kernel,
                         cudaFuncAttributeMaxDynamicSharedMemorySize, SM_GEMM);
    cudaFuncSetAttribute(hgemm2_kernel,
                         cudaFuncAttributeMaxDynamicSharedMemorySize, SM_GEMM);
    cudaFuncSetAttribute(attn_hmma_kernel,
                         cudaFuncAttributeMaxDynamicSharedMemorySize, SM_ATTN);

    dim3 ggrid(8, 32);
    dim3 ggrid2(8, 32, 2);
    const float qscale = 0.125f * 1.4426950408889634f;  // 1/sqrt(hd) * log2(e)

    // launch 2: Q projection
    hgemm_kernel<<<ggrid, 256, SM_GEMM>>>(xh, Wt + 0u * 1048576u, b0, Qh, nullptr, 0, 2048, 0, qscale);
    // launch 3: K projection (self + context fused)
    hgemm2_kernel<<<ggrid2, 256, SM_GEMM>>>(xh, ch, Wt + 1u * 1048576u, Wt + 3u * 1048576u, b1, b3, Kh);
    // launch 4: V projection (self + context fused)
    hgemm2_kernel<<<ggrid2, 256, SM_GEMM>>>(xh, ch, Wt + 2u * 1048576u, Wt + 4u * 1048576u, b2, b4, Vh);

    // launch 5: attention
    dim3 agrid(16, 16, 2);
    attn_hmma_kernel<<<agrid, 256, SM_ATTN>>>(Qh, Kh, Vh, Oh);

    // launch 6: output projection (fp32 out)
    hgemm_kernel<<<ggrid, 256, SM_GEMM>>>(Oh, Wt + 5u * 1048576u, b5, nullptr, out, 1, 2048, 0, 1.0f);
}

// round 8
// speedup vs baseline: 6.2137x; 1.0120x over previous
#include <cuda_runtime.h>
#include <cuda_fp16.h>
#include <stdint.h>
#include <math.h>

// Shapes: B=2, Tq=2048, Tctx=2048 -> Tk=4096, D=1024, H=16, hd=64
#define GK 1024
#define GN 1024

// ---------------- persistent fp16 scratch ----------------
__device__ __half g_xh[4194304];            // x fp16    [4096][1024]
__device__ __half g_ch[4194304];            // ctx fp16  [4096][1024]
__device__ __half g_Wt[6][1048576];         // W^T fp16  [1024 n][1024 k]
__device__ __half g_Qh[4194304];            // Q (scaled)[2*2048][1024]
__device__ __half g_Kh[8388608];            // K concat  [2*4096][1024]
__device__ __half g_Vh[8388608];            // V concat  [2*4096][1024]
__device__ __half g_Oh[4194304];            // attn out  [2*2048][1024]

// ---------------- ptx helpers ----------------
__device__ __forceinline__ uint32_t smem_u32(const void* p) {
    return static_cast<uint32_t>(__cvta_generic_to_shared(p));
}
__device__ __forceinline__ void cp16(uint32_t dst, const void* src) {
    asm volatile("cp.async.cg.shared.global [%0], [%1], 16;" :: "r"(dst), "l"(src));
}
__device__ __forceinline__ void cp_commit() {
    asm volatile("cp.async.commit_group;" ::: "memory");
}
__device__ __forceinline__ void cp_wait1() {
    asm volatile("cp.async.wait_group 1;" ::: "memory");
}
__device__ __forceinline__ void ldsm_x4(uint32_t* r, uint32_t addr) {
    asm volatile("ldmatrix.sync.aligned.m8n8.x4.shared.b16 {%0,%1,%2,%3}, [%4];"
                 : "=r"(r[0]), "=r"(r[1]), "=r"(r[2]), "=r"(r[3]) : "r"(addr));
}
__device__ __forceinline__ void ldsm_x4t(uint32_t* r, uint32_t addr) {
    asm volatile("ldmatrix.sync.aligned.m8n8.x4.trans.shared.b16 {%0,%1,%2,%3}, [%4];"
                 : "=r"(r[0]), "=r"(r[1]), "=r"(r[2]), "=r"(r[3]) : "r"(addr));
}
__device__ __forceinline__ void mma16816(float* c, const uint32_t* a, const uint32_t* b) {
    asm volatile(
        "mma.sync.aligned.m16n8k16.row.col.f32.f16.f16.f32 "
        "{%0,%1,%2,%3}, {%4,%5,%6,%7}, {%8,%9}, {%0,%1,%2,%3};"
        : "+f"(c[0]), "+f"(c[1]), "+f"(c[2]), "+f"(c[3])
        : "r"(a[0]), "r"(a[1]), "r"(a[2]), "r"(a[3]), "r"(b[0]), "r"(b[1]));
}
__device__ __forceinline__ uint32_t pack_h2(float lo, float hi) {
    __half2 h;
    h.x = __float2half_rn(lo);
    h.y = __float2half_rn(hi);
    uint32_t u;
    memcpy(&u, &h, 4);
    return u;
}
__device__ __forceinline__ uint32_t h2exp2(uint32_t x) {
    uint32_t r;
    asm volatile("ex2.approx.f16x2 %0, %1;" : "=r"(r) : "r"(x));
    return r;
}

// ---------------- fused fp32 -> fp16 convert (z selects tensor) ----------
__global__ void f2h2_kernel(const float* __restrict__ in0, const float* __restrict__ in1,
                            __half* __restrict__ out0, __half* __restrict__ out1, int n4) {
    const float* in = blockIdx.z ? in1 : in0;
    __half* out = blockIdx.z ? out1 : out0;
    int i = blockIdx.x * blockDim.x + threadIdx.x;
    if (i < n4) {
        float4 v = reinterpret_cast<const float4*>(in)[i];
        __half2 a; a.x = __float2half_rn(v.x); a.y = __float2half_rn(v.y);
        __half2 b; b.x = __float2half_rn(v.z); b.y = __float2half_rn(v.w);
        reinterpret_cast<__half2*>(out)[i * 2]     = a;
        reinterpret_cast<__half2*>(out)[i * 2 + 1] = b;
    }
}

// ---------------- fused W [K][N] fp32 -> Wt [N][K] fp16 (z = weight idx) ----
__global__ void wtrans6_kernel(const float* w0, const float* w1, const float* w2,
                               const float* w3, const float* w4, const float* w5,
                               __half* __restrict__ WtBase) {
    __shared__ float t[32][33];
    const float* W;
    switch (blockIdx.z) {
        case 0: W = w0; break;
        case 1: W = w1; break;
        case 2: W = w2; break;
        case 3: W = w3; break;
        case 4: W = w4; break;
        default: W = w5; break;
    }
    __half* Wt = WtBase + (size_t)blockIdx.z * 1048576u;
    int n0 = blockIdx.x * 32, k0 = blockIdx.y * 32;
    int tx = threadIdx.x, ty = threadIdx.y;
#pragma unroll
    for (int i = 0; i < 32; i += 8)
        t[ty + i][tx] = W[(size_t)(k0 + ty + i) * GN + n0 + tx];
    __syncthreads();
#pragma unroll
    for (int i = 0; i < 32; i += 8)
        Wt[(size_t)(n0 + ty + i) * GK + k0 + tx] = __float2half_rn(t[tx][ty + i]);
}

// ---------------- HMMA GEMM, 3-stage cp.async pipeline ----------------
#define TSZ 10240
#define A_OFF(s) ((s) * TSZ)
#define B_OFF(s) (3 * TSZ + (s) * TSZ)
#define SM_GEMM (6 * TSZ)

__device__ __forceinline__ void hgemm_body(
    const __half* __restrict__ A, const __half* __restrict__ Bt,
    const float* __restrict__ bias, __half* __restrict__ outH,
    float* __restrict__ outF, int f32out, int bstride, int roff, float scale,
    char* smem)
{
    const uint32_t sb = smem_u32(smem);
    const int tid = threadIdx.x;
    const int lane = tid & 31;
    const int wid = tid >> 5;
    const int wm = (wid >> 2) * 64;
    const int wn = (wid & 3) * 32;
    const int row0 = blockIdx.y * 128;
    const int col0 = blockIdx.x * 128;

    const __half* Ag = A + (size_t)row0 * GK;
    const __half* Bg = Bt + (size_t)col0 * GK;

#define GLOAD(kc, s)                                                         \
    {                                                                        \
        _Pragma("unroll")                                                    \
        for (int j = 0; j < 2; j++) {                                        \
            int idx = tid + j * 256;                                         \
            int r = idx >> 2;                                                \
            int cb = (idx & 3) * 8;                                          \
            cp16(sb + A_OFF(s) + r * 80 + cb * 2,                            \
                 Ag + (size_t)r * GK + (kc) * 32 + cb);                      \
            cp16(sb + B_OFF(s) + r * 80 + cb * 2,                            \
                 Bg + (size_t)r * GK + (kc) * 32 + cb);                      \
        }                                                                    \
    }

    float acc[4][4][4];
#pragma unroll
    for (int i = 0; i < 4; i++)
#pragma unroll
        for (int j = 0; j < 4; j++)
#pragma unroll
            for (int k = 0; k < 4; k++) acc[i][j][k] = 0.f;

    GLOAD(0, 0); cp_commit();
    GLOAD(1, 1); cp_commit();

    const int mat = lane >> 3;      // x4 matrix index
    const int mrow = lane & 7;

    for (int c = 0; c < 32; c++) {
        const int s = c % 3;
        cp_wait1();
        __syncthreads();
        if (c + 2 < 32) GLOAD(c + 2, (c + 2) % 3);
        cp_commit();

#pragma unroll
        for (int ks = 0; ks < 2; ks++) {
            uint32_t af[4][4];
#pragma unroll
            for (int mt = 0; mt < 4; mt++) {
                int row = wm + mt * 16 + (lane & 7) + (lane & 8);
                int col = ks * 16 + (lane >> 4) * 8;
                ldsm_x4(af[mt], sb + A_OFF(s) + (row * 40 + col) * 2);
            }
            // B fragments: x4 loads fragments nt and nt+1 together
            uint32_t bf[4][2];
#pragma unroll
            for (int np = 0; np < 2; np++) {
                int row = wn + (np * 2 + (mat >> 1)) * 8 + mrow;
                int col = ks * 16 + (mat & 1) * 8;
                uint32_t r4[4];
                ldsm_x4(r4, sb + B_OFF(s) + (row * 40 + col) * 2);
                bf[np * 2][0] = r4[0];     bf[np * 2][1] = r4[1];
                bf[np * 2 + 1][0] = r4[2]; bf[np * 2 + 1][1] = r4[3];
            }
#pragma unroll
            for (int mt = 0; mt < 4; mt++)
#pragma unroll
                for (int nt = 0; nt < 4; nt++)
                    mma16816(acc[mt][nt], af[mt], bf[nt]);
        }
    }

    const int g = lane >> 2;
    const int qd = lane & 3;
#pragma unroll
    for (int mt = 0; mt < 4; mt++) {
        int r0 = row0 + wm + mt * 16 + g;
        int r1 = r0 + 8;
        size_t or0 = (size_t)((r0 >> 11) * bstride + (r0 & 2047) + roff);
        size_t or1 = (size_t)((r1 >> 11) * bstride + (r1 & 2047) + roff);
#pragma unroll
        for (int nt = 0; nt < 4; nt++) {
            int col = col0 + wn + nt * 8 + qd * 2;
            float b0 = bias[col];
            float b1 = bias[col + 1];
            float v00 = (acc[mt][nt][0] + b0) * scale;
            float v01 = (acc[mt][nt][1] + b1) * scale;
            float v10 = (acc[mt][nt][2] + b0) * scale;
            float v11 = (acc[mt][nt][3] + b1) * scale;
            if (f32out) {
                outF[or0 * GN + col]     = v00;
                outF[or0 * GN + col + 1] = v01;
                outF[or1 * GN + col]     = v10;
                outF[or1 * GN + col + 1] = v11;
            } else {
                *reinterpret_cast<uint32_t*>(&outH[or0 * GN + col]) = pack_h2(v00, v01);
                *reinterpret_cast<uint32_t*>(&outH[or1 * GN + col]) = pack_h2(v10, v11);
            }
        }
    }
}

__global__ __launch_bounds__(256) void hgemm_kernel(
    const __half* __restrict__ A, const __half* __restrict__ Bt,
    const float* __restrict__ bias, __half* __restrict__ outH,
    float* __restrict__ outF, int f32out, int bstride, int roff, float scale)
{
    extern __shared__ char smem[];
    hgemm_body(A, Bt, bias, outH, outF, f32out, bstride, roff, scale, smem);
}

__global__ __launch_bounds__(256) void hgemm2_kernel(
    const __half* __restrict__ A0, const __half* __restrict__ A1,
    const __half* __restrict__ Bt0, const __half* __restrict__ Bt1,
    const float* __restrict__ bias0, const float* __restrict__ bias1,
    __half* __restrict__ outH)
{
    extern __shared__ char smem[];
    if (blockIdx.z == 0)
        hgemm_body(A0, Bt0, bias0, outH, nullptr, 0, 4096, 0, 1.0f, smem);
    else
        hgemm_body(A1, Bt1, bias1, outH, nullptr, 0, 4096, 2048, 1.0f, smem);
}

// ---------------- flash attention (HMMA) ----------------
// 3-stage cp.async K/V ring, x4 ldmatrix (paired fragments), fp16x2 exp,
// ones-MMA row sums.
#define KVSTG 18432
#define KOFF(s) ((s) * KVSTG)
#define VOFF(s) ((s) * KVSTG + 9216)
#define SM_ATTN (3 * KVSTG)

__global__ __launch_bounds__(256, 2) void attn_hmma_kernel(
    const __half* __restrict__ Q, const __half* __restrict__ K,
    const __half* __restrict__ V, __half* __restrict__ O)
{
    extern __shared__ char smem[];
    const uint32_t sb = smem_u32(smem);

    const int tid = threadIdx.x;
    const int lane = tid & 31;
    const int wid = tid >> 5;
    const int qt = blockIdx.x;
    const int h = blockIdx.y;
    const int b = blockIdx.z;
    const int q0 = qt * 128 + wid * 16;
    const int g = lane >> 2;
    const int qd = lane & 3;
    const int mat = lane >> 3;
    const int mrow = lane & 7;

    const __half* Qb = Q + ((size_t)b * 2048 + q0) * GN + h * 64;
    const __half* Kb = K + (size_t)b * 4096 * GN + h * 64;
    const __half* Vb = V + (size_t)b * 4096 * GN + h * 64;

    // Q fragments (A operand)
    uint32_t qf[4][4];
#pragma unroll
    for (int ks = 0; ks < 4; ks++) {
        int c0 = ks * 16 + qd * 2;
        qf[ks][0] = *reinterpret_cast<const uint32_t*>(Qb + (size_t)g * GN + c0);
        qf[ks][1] = *reinterpret_cast<const uint32_t*>(Qb + (size_t)(g + 8) * GN + c0);
        qf[ks][2] = *reinterpret_cast<const uint32_t*>(Qb + (size_t)g * GN + c0 + 8);
        qf[ks][3] = *reinterpret_cast<const uint32_t*>(Qb + (size_t)(g + 8) * GN + c0 + 8);
    }

    float of[8][4];
#pragma unroll
    for (int i = 0; i < 8; i++)
#pragma unroll
        for (int j = 0; j < 4; j++) of[i][j] = 0.f;
    float ls[4] = {0.f, 0.f, 0.f, 0.f};
    float m0 = -1e30f, m1 = -1e30f;

    const uint32_t ONES2 = 0x3C003C00u;
    const uint32_t onesb[2] = {ONES2, ONES2};

    const int lr = tid & 63;
    const int lc = (tid >> 6) * 16;

#define LOAD_KV(kb, s)                                                       \
    {                                                                        \
        const __half* Kg = Kb + (size_t)((kb) * 64 + lr) * GN + lc;          \
        const __half* Vg = Vb + (size_t)((kb) * 64 + lr) * GN + lc;          \
        cp16(sb + KOFF(s) + (lr * 72 + lc) * 2, Kg);                         \
        cp16(sb + KOFF(s) + (lr * 72 + lc + 8) * 2, Kg + 8);                 \
        cp16(sb + VOFF(s) + (lr * 72 + lc) * 2, Vg);                         \
        cp16(sb + VOFF(s) + (lr * 72 + lc + 8) * 2, Vg + 8);                 \
    }

    LOAD_KV(0, 0); cp_commit();
    LOAD_KV(1, 1); cp_commit();

    for (int kb = 0; kb < 64; kb++) {
        const int s = kb % 3;
        cp_wait1();
        __syncthreads();
        if (kb + 2 < 64) LOAD_KV(kb + 2, (kb + 2) % 3);
        cp_commit();

        const uint32_t sK = sb + KOFF(s);
        const uint32_t sV = sb + VOFF(s);

        // S = Qs @ K^T : x4 loads fragment pairs (nt, nt+1)
        float sc[8][4];
#pragma unroll
        for (int nt = 0; nt < 8; nt++) {
            sc[nt][0] = 0.f; sc[nt][1] = 0.f; sc[nt][2] = 0.f; sc[nt][3] = 0.f;
        }
#pragma unroll
        for (int ks = 0; ks < 4; ks++) {
            uint32_t bf[8][2];
#pragma unroll
            for (int np = 0; np < 4; np++) {
                int row = (np * 2 + (mat >> 1)) * 8 + mrow;
                int col = ks * 16 + (mat & 1) * 8;
                uint32_t r4[4];
                ldsm_x4(r4, sK + (row * 72 + col) * 2);
                bf[np * 2][0] = r4[0];     bf[np * 2][1] = r4[1];
                bf[np * 2 + 1][0] = r4[2]; bf[np * 2 + 1][1] = r4[3];
            }
#pragma unroll
            for (int nt = 0; nt < 8; nt++)
                mma16816(sc[nt], qf[ks], bf[nt]);
        }

        // online softmax max-reduce
        float mx0 = -1e30f, mx1 = -1e30f;
#pragma unroll
        for (int nt = 0; nt < 8; nt++) {
            mx0 = fmaxf(mx0, fmaxf(sc[nt][0], sc[nt][1]));
            mx1 = fmaxf(mx1, fmaxf(sc[nt][2], sc[nt][3]));
        }
        mx0 = fmaxf(mx0, __shfl_xor_sync(0xffffffffu, mx0, 1));
        mx0 = fmaxf(mx0, __shfl_xor_sync(0xffffffffu, mx0, 2));
        mx1 = fmaxf(mx1, __shfl_xor_sync(0xffffffffu, mx1, 1));
        mx1 = fmaxf(mx1, __shfl_xor_sync(0xffffffffu, mx1, 2));
        float nm0 = fmaxf(m0, mx0);
        float nm1 = fmaxf(m1, mx1);
        float cr0 = exp2f(m0 - nm0);
        float cr1 = exp2f(m1 - nm1);
        m0 = nm0;
        m1 = nm1;

        ls[0] *= cr0; ls[1] *= cr0; ls[2] *= cr1; ls[3] *= cr1;
#pragma unroll
        for (int dn = 0; dn < 8; dn++) {
            of[dn][0] *= cr0; of[dn][1] *= cr0;
            of[dn][2] *= cr1; of[dn][3] *= cr1;
        }

        // P = exp2(S - m) in fp16x2 (A-fragment layout)
        uint32_t pf[4][4];
#pragma unroll
        for (int kp = 0; kp < 4; kp++) {
            pf[kp][0] = h2exp2(pack_h2(sc[2 * kp][0] - nm0,     sc[2 * kp][1] - nm0));
            pf[kp][1] = h2exp2(pack_h2(sc[2 * kp][2] - nm1,     sc[2 * kp][3] - nm1));
            pf[kp][2] = h2exp2(pack_h2(sc[2 * kp + 1][0] - nm0, sc[2 * kp + 1][1] - nm0));
            pf[kp][3] = h2exp2(pack_h2(sc[2 * kp + 1][2] - nm1, sc[2 * kp + 1][3] - nm1));
        }

        // row sums via ones-MMA
#pragma unroll
        for (int kp = 0; kp < 4; kp++)
            mma16816(ls, pf[kp], onesb);

        // O += P @ V : x4.trans loads fragment pairs (dn, dn+1)
#pragma unroll
        for (int kp = 0; kp < 4; kp++) {
            uint32_t vf[8][2];
#pragma unroll
            for (int dp = 0; dp < 4; dp++) {
                int row = kp * 16 + (mat & 1) * 8 + mrow;
                int col = (dp * 2 + (mat >> 1)) * 8;
                uint32_t r4[4];
                ldsm_x4t(r4, sV + (row * 72 + col) * 2);
                vf[dp * 2][0] = r4[0];     vf[dp * 2][1] = r4[1];
                vf[dp * 2 + 1][0] = r4[2]; vf[dp * 2 + 1][1] = r4[3];
            }
#pragma unroll
            for (int dn = 0; dn < 8; dn++)
                mma16816(of[dn], pf[kp], vf[dn]);
        }
    }

    // epilogue
    float inv0 = 1.f / ls[0];
    float inv1 = 1.f / ls[2];
    __half* Ob = O + ((size_t)b * 2048 + q0) * GN + h * 64;
#pragma unroll
    for (int dn = 0; dn < 8; dn++) {
        int col = dn * 8 + qd * 2;
        *reinterpret_cast<uint32_t*>(Ob + (size_t)g * GN + col) =
            pack_h2(of[dn][0] * inv0, of[dn][1] * inv0);
        *reinterpret_cast<uint32_t*>(Ob + (size_t)(g + 8) * GN + col) =
            pack_h2(of[dn][2] * inv1, of[dn][3] * inv1);
    }
}

// ---------------------------------------------------------------------------
extern "C" void kernel_launch(void* const* d_in, const int* in_sizes, int n_in,
                              void* d_out, int out_size)
{
    const float* x   = (const float*)d_in[0];
    const float* ctx = (const float*)d_in[1];
    const float* W0  = (const float*)d_in[2];   // Wq
    const float* b0  = (const float*)d_in[3];
    const float* W1  = (const float*)d_in[4];   // Wks
    const float* b1  = (const float*)d_in[5];
    const float* W2  = (const float*)d_in[6];   // Wvs
    const float* b2  = (const float*)d_in[7];
    const float* W3  = (const float*)d_in[8];   // Wkc
    const float* b3  = (const float*)d_in[9];
    const float* W4  = (const float*)d_in[10];  // Wvc
    const float* b4  = (const float*)d_in[11];
    const float* W5  = (const float*)d_in[12];  // Wo
    const float* b5  = (const float*)d_in[13];
    float* out = (float*)d_out;

    __half* xh;
    __half* ch;
    __half* Wt;
    __half* Qh;
    __half* Kh;
    __half* Vh;
    __half* Oh;
    cudaGetSymbolAddress((void**)&xh, g_xh);
    cudaGetSymbolAddress((void**)&ch, g_ch);
    cudaGetSymbolAddress((void**)&Wt, g_Wt);
    cudaGetSymbolAddress((void**)&Qh, g_Qh);
    cudaGetSymbolAddress((void**)&Kh, g_Kh);
    cudaGetSymbolAddress((void**)&Vh, g_Vh);
    cudaGetSymbolAddress((void**)&Oh, g_Oh);

    // launch 0: fp32 -> fp16 inputs (fused)
    dim3 fgrid(4096, 1, 2);
    f2h2_kernel<<<fgrid, 256>>>(x, ctx, xh, ch, 1048576);

    // launch 1: weights transpose-convert (fused)
    dim3 wgrid(32, 32, 6);
    dim3 wblk(32, 8);
    wtrans6_kernel<<<wgrid, wblk>>>(W0, W1, W2, W3, W4, W5, Wt);

    cudaFuncSetAttribute(hgemm_kernel,
                         cudaFuncAttributeMaxDynamicSharedMemorySize, SM_GEMM);
    cudaFuncSetAttribute(hgemm2_kernel,
                         cudaFuncAttributeMaxDynamicSharedMemorySize, SM_GEMM);
    cudaFuncSetAttribute(attn_hmma_kernel,
                         cudaFuncAttributeMaxDynamicSharedMemorySize, SM_ATTN);

    dim3 ggrid(8, 32);
    dim3 ggrid2(8, 32, 2);
    const float qscale = 0.125f * 1.4426950408889634f;  // 1/sqrt(hd) * log2(e)

    // launch 2: Q projection
    hgemm_kernel<<<ggrid, 256, SM_GEMM>>>(xh, Wt + 0u * 1048576u, b0, Qh, nullptr, 0, 2048, 0, qscale);
    // launch 3: K projection (self + context fused)
    hgemm2_kernel<<<ggrid2, 256, SM_GEMM>>>(xh, ch, Wt + 1u * 1048576u, Wt + 3u * 1048576u, b1, b3, Kh);
    // launch 4: V projection (self + context fused)
    hgemm2_kernel<<<ggrid2, 256, SM_GEMM>>>(xh, ch, Wt + 2u * 1048576u, Wt + 4u * 1048576u, b2, b4, Vh);

    // launch 5: attention
    dim3 agrid(16, 16, 2);
    attn_hmma_kernel<<<agrid, 256, SM_ATTN>>>(Qh, Kh, Vh, Oh);

    // launch 6: output projection (fp32 out)
    hgemm_kernel<<<ggrid, 256, SM_GEMM>>>(Oh, Wt + 5u * 1048576u, b5, nullptr, out, 1, 2048, 0, 1.0f);
}

// round 9
// speedup vs baseline: 6.4776x; 1.0425x over previous
#include <cuda_runtime.h>
#include <cuda_fp16.h>
#include <stdint.h>
#include <math.h>

// Shapes: B=2, Tq=2048, Tctx=2048 -> Tk=4096, D=1024, H=16, hd=64
#define GK 1024
#define GN 1024

// ---------------- persistent fp16 scratch ----------------
__device__ __half g_xh[4194304];            // x fp16    [4096][1024]
__device__ __half g_ch[4194304];            // ctx fp16  [4096][1024]
__device__ __half g_Wt[6][1048576];         // W^T fp16  [1024 n][1024 k]
__device__ __half g_Qh[4194304];            // Q (scaled)[2*2048][1024]
__device__ __half g_Kh[8388608];            // K concat  [2*4096][1024]
__device__ __half g_Vh[8388608];            // V concat  [2*4096][1024]
__device__ __half g_Oh[4194304];            // attn out  [2*2048][1024]

// ---------------- ptx helpers ----------------
__device__ __forceinline__ uint32_t smem_u32(const void* p) {
    return static_cast<uint32_t>(__cvta_generic_to_shared(p));
}
__device__ __forceinline__ void cp16(uint32_t dst, const void* src) {
    asm volatile("cp.async.cg.shared.global [%0], [%1], 16;" :: "r"(dst), "l"(src));
}
__device__ __forceinline__ void cp_commit() {
    asm volatile("cp.async.commit_group;" ::: "memory");
}
__device__ __forceinline__ void cp_wait1() {
    asm volatile("cp.async.wait_group 1;" ::: "memory");
}
__device__ __forceinline__ void ldsm_x4(uint32_t* r, uint32_t addr) {
    asm volatile("ldmatrix.sync.aligned.m8n8.x4.shared.b16 {%0,%1,%2,%3}, [%4];"
                 : "=r"(r[0]), "=r"(r[1]), "=r"(r[2]), "=r"(r[3]) : "r"(addr));
}
__device__ __forceinline__ void ldsm_x4t(uint32_t* r, uint32_t addr) {
    asm volatile("ldmatrix.sync.aligned.m8n8.x4.trans.shared.b16 {%0,%1,%2,%3}, [%4];"
                 : "=r"(r[0]), "=r"(r[1]), "=r"(r[2]), "=r"(r[3]) : "r"(addr));
}
__device__ __forceinline__ void mma16816(float* c, const uint32_t* a, const uint32_t* b) {
    asm volatile(
        "mma.sync.aligned.m16n8k16.row.col.f32.f16.f16.f32 "
        "{%0,%1,%2,%3}, {%4,%5,%6,%7}, {%8,%9}, {%0,%1,%2,%3};"
        : "+f"(c[0]), "+f"(c[1]), "+f"(c[2]), "+f"(c[3])
        : "r"(a[0]), "r"(a[1]), "r"(a[2]), "r"(a[3]), "r"(b[0]), "r"(b[1]));
}
__device__ __forceinline__ uint32_t pack_h2(float lo, float hi) {
    __half2 h;
    h.x = __float2half_rn(lo);
    h.y = __float2half_rn(hi);
    uint32_t u;
    memcpy(&u, &h, 4);
    return u;
}
__device__ __forceinline__ uint32_t h2exp2(uint32_t x) {
    uint32_t r;
    asm volatile("ex2.approx.f16x2 %0, %1;" : "=r"(r) : "r"(x));
    return r;
}

// ---------------- fused fp32 -> fp16 convert (z selects tensor) ----------
__global__ void f2h2_kernel(const float* __restrict__ in0, const float* __restrict__ in1,
                            __half* __restrict__ out0, __half* __restrict__ out1, int n4) {
    const float* in = blockIdx.z ? in1 : in0;
    __half* out = blockIdx.z ? out1 : out0;
    int i = blockIdx.x * blockDim.x + threadIdx.x;
    if (i < n4) {
        float4 v = reinterpret_cast<const float4*>(in)[i];
        __half2 a; a.x = __float2half_rn(v.x); a.y = __float2half_rn(v.y);
        __half2 b; b.x = __float2half_rn(v.z); b.y = __float2half_rn(v.w);
        reinterpret_cast<__half2*>(out)[i * 2]     = a;
        reinterpret_cast<__half2*>(out)[i * 2 + 1] = b;
    }
}

// ---------------- fused W [K][N] fp32 -> Wt [N][K] fp16 (z = weight idx) ----
__global__ void wtrans6_kernel(const float* w0, const float* w1, const float* w2,
                               const float* w3, const float* w4, const float* w5,
                               __half* __restrict__ WtBase) {
    __shared__ float t[32][33];
    const float* W;
    switch (blockIdx.z) {
        case 0: W = w0; break;
        case 1: W = w1; break;
        case 2: W = w2; break;
        case 3: W = w3; break;
        case 4: W = w4; break;
        default: W = w5; break;
    }
    __half* Wt = WtBase + (size_t)blockIdx.z * 1048576u;
    int n0 = blockIdx.x * 32, k0 = blockIdx.y * 32;
    int tx = threadIdx.x, ty = threadIdx.y;
#pragma unroll
    for (int i = 0; i < 32; i += 8)
        t[ty + i][tx] = W[(size_t)(k0 + ty + i) * GN + n0 + tx];
    __syncthreads();
#pragma unroll
    for (int i = 0; i < 32; i += 8)
        Wt[(size_t)(n0 + ty + i) * GK + k0 + tx] = __float2half_rn(t[tx][ty + i]);
}

// ---------------- HMMA GEMM, 3-stage cp.async pipeline ----------------
// 512 threads, 16 warps (4m x 4n), warp tile 32x32 -> low regs, 2 CTAs/SM,
// 32 warps/SM. CTA tile 128x128, BK=32.
#define TSZ 10240
#define A_OFF(s) ((s) * TSZ)
#define B_OFF(s) (3 * TSZ + (s) * TSZ)
#define SM_GEMM (6 * TSZ)

__device__ __forceinline__ void hgemm_body(
    const __half* __restrict__ A, const __half* __restrict__ Bt,
    const float* __restrict__ bias, __half* __restrict__ outH,
    float* __restrict__ outF, int f32out, int bstride, int roff, float scale,
    char* smem)
{
    const uint32_t sb = smem_u32(smem);
    const int tid = threadIdx.x;
    const int lane = tid & 31;
    const int wid = tid >> 5;                 // 0..15
    const int wm = (wid >> 2) * 32;           // 4 m-groups of 32 rows
    const int wn = (wid & 3) * 32;            // 4 n-groups of 32 cols
    const int row0 = blockIdx.y * 128;
    const int col0 = blockIdx.x * 128;

    const __half* Ag = A + (size_t)row0 * GK;
    const __half* Bg = Bt + (size_t)col0 * GK;

    // per chunk: A 128x32 halves = 512 x 16B -> 1 cp16 per thread (ditto B)
#define GLOAD(kc, s)                                                         \
    {                                                                        \
        int r = tid >> 2;                                                    \
        int cb = (tid & 3) * 8;                                              \
        cp16(sb + A_OFF(s) + r * 80 + cb * 2,                                \
             Ag + (size_t)r * GK + (kc) * 32 + cb);                          \
        cp16(sb + B_OFF(s) + r * 80 + cb * 2,                                \
             Bg + (size_t)r * GK + (kc) * 32 + cb);                          \
    }

    float acc[2][4][4];
#pragma unroll
    for (int i = 0; i < 2; i++)
#pragma unroll
        for (int j = 0; j < 4; j++)
#pragma unroll
            for (int k = 0; k < 4; k++) acc[i][j][k] = 0.f;

    GLOAD(0, 0); cp_commit();
    GLOAD(1, 1); cp_commit();

    const int mat = lane >> 3;
    const int mrow = lane & 7;

    for (int c = 0; c < 32; c++) {
        const int s = c % 3;
        cp_wait1();
        __syncthreads();
        if (c + 2 < 32) GLOAD(c + 2, (c + 2) % 3);
        cp_commit();

#pragma unroll
        for (int ks = 0; ks < 2; ks++) {
            uint32_t af[2][4];
#pragma unroll
            for (int mt = 0; mt < 2; mt++) {
                int row = wm + mt * 16 + (lane & 7) + (lane & 8);
                int col = ks * 16 + (lane >> 4) * 8;
                ldsm_x4(af[mt], sb + A_OFF(s) + (row * 40 + col) * 2);
            }
            uint32_t bf[4][2];
#pragma unroll
            for (int np = 0; np < 2; np++) {
                int row = wn + (np * 2 + (mat >> 1)) * 8 + mrow;
                int col = ks * 16 + (mat & 1) * 8;
                uint32_t r4[4];
                ldsm_x4(r4, sb + B_OFF(s) + (row * 40 + col) * 2);
                bf[np * 2][0] = r4[0];     bf[np * 2][1] = r4[1];
                bf[np * 2 + 1][0] = r4[2]; bf[np * 2 + 1][1] = r4[3];
            }
#pragma unroll
            for (int mt = 0; mt < 2; mt++)
#pragma unroll
                for (int nt = 0; nt < 4; nt++)
                    mma16816(acc[mt][nt], af[mt], bf[nt]);
        }
    }

    const int g = lane >> 2;
    const int qd = lane & 3;
#pragma unroll
    for (int mt = 0; mt < 2; mt++) {
        int r0 = row0 + wm + mt * 16 + g;
        int r1 = r0 + 8;
        size_t or0 = (size_t)((r0 >> 11) * bstride + (r0 & 2047) + roff);
        size_t or1 = (size_t)((r1 >> 11) * bstride + (r1 & 2047) + roff);
#pragma unroll
        for (int nt = 0; nt < 4; nt++) {
            int col = col0 + wn + nt * 8 + qd * 2;
            float b0 = bias[col];
            float b1 = bias[col + 1];
            float v00 = (acc[mt][nt][0] + b0) * scale;
            float v01 = (acc[mt][nt][1] + b1) * scale;
            float v10 = (acc[mt][nt][2] + b0) * scale;
            float v11 = (acc[mt][nt][3] + b1) * scale;
            if (f32out) {
                outF[or0 * GN + col]     = v00;
                outF[or0 * GN + col + 1] = v01;
                outF[or1 * GN + col]     = v10;
                outF[or1 * GN + col + 1] = v11;
            } else {
                *reinterpret_cast<uint32_t*>(&outH[or0 * GN + col]) = pack_h2(v00, v01);
                *reinterpret_cast<uint32_t*>(&outH[or1 * GN + col]) = pack_h2(v10, v11);
            }
        }
    }
}

__global__ __launch_bounds__(512, 2) void hgemm_kernel(
    const __half* __restrict__ A, const __half* __restrict__ Bt,
    const float* __restrict__ bias, __half* __restrict__ outH,
    float* __restrict__ outF, int f32out, int bstride, int roff, float scale)
{
    extern __shared__ char smem[];
    hgemm_body(A, Bt, bias, outH, outF, f32out, bstride, roff, scale, smem);
}

__global__ __launch_bounds__(512, 2) void hgemm2_kernel(
    const __half* __restrict__ A0, const __half* __restrict__ A1,
    const __half* __restrict__ Bt0, const __half* __restrict__ Bt1,
    const float* __restrict__ bias0, const float* __restrict__ bias1,
    __half* __restrict__ outH)
{
    extern __shared__ char smem[];
    if (blockIdx.z == 0)
        hgemm_body(A0, Bt0, bias0, outH, nullptr, 0, 4096, 0, 1.0f, smem);
    else
        hgemm_body(A1, Bt1, bias1, outH, nullptr, 0, 4096, 2048, 1.0f, smem);
}

// ---------------- flash attention (HMMA) ----------------
// 3-stage cp.async K/V ring, x4 ldmatrix, fp16x2 exp, ones-MMA row sums,
// warp-uniform skip of softmax rescale when running max is unchanged.
#define KVSTG 18432
#define KOFF(s) ((s) * KVSTG)
#define VOFF(s) ((s) * KVSTG + 9216)
#define SM_ATTN (3 * KVSTG)

__global__ __launch_bounds__(256, 2) void attn_hmma_kernel(
    const __half* __restrict__ Q, const __half* __restrict__ K,
    const __half* __restrict__ V, __half* __restrict__ O)
{
    extern __shared__ char smem[];
    const uint32_t sb = smem_u32(smem);

    const int tid = threadIdx.x;
    const int lane = tid & 31;
    const int wid = tid >> 5;
    const int qt = blockIdx.x;
    const int h = blockIdx.y;
    const int b = blockIdx.z;
    const int q0 = qt * 128 + wid * 16;
    const int g = lane >> 2;
    const int qd = lane & 3;
    const int mat = lane >> 3;
    const int mrow = lane & 7;

    const __half* Qb = Q + ((size_t)b * 2048 + q0) * GN + h * 64;
    const __half* Kb = K + (size_t)b * 4096 * GN + h * 64;
    const __half* Vb = V + (size_t)b * 4096 * GN + h * 64;

    // Q fragments (A operand)
    uint32_t qf[4][4];
#pragma unroll
    for (int ks = 0; ks < 4; ks++) {
        int c0 = ks * 16 + qd * 2;
        qf[ks][0] = *reinterpret_cast<const uint32_t*>(Qb + (size_t)g * GN + c0);
        qf[ks][1] = *reinterpret_cast<const uint32_t*>(Qb + (size_t)(g + 8) * GN + c0);
        qf[ks][2] = *reinterpret_cast<const uint32_t*>(Qb + (size_t)g * GN + c0 + 8);
        qf[ks][3] = *reinterpret_cast<const uint32_t*>(Qb + (size_t)(g + 8) * GN + c0 + 8);
    }

    float of[8][4];
#pragma unroll
    for (int i = 0; i < 8; i++)
#pragma unroll
        for (int j = 0; j < 4; j++) of[i][j] = 0.f;
    float ls[4] = {0.f, 0.f, 0.f, 0.f};
    float m0 = -1e30f, m1 = -1e30f;

    const uint32_t ONES2 = 0x3C003C00u;
    const uint32_t onesb[2] = {ONES2, ONES2};

    const int lr = tid & 63;
    const int lc = (tid >> 6) * 16;

#define LOAD_KV(kb, s)                                                       \
    {                                                                        \
        const __half* Kg = Kb + (size_t)((kb) * 64 + lr) * GN + lc;          \
        const __half* Vg = Vb + (size_t)((kb) * 64 + lr) * GN + lc;          \
        cp16(sb + KOFF(s) + (lr * 72 + lc) * 2, Kg);                         \
        cp16(sb + KOFF(s) + (lr * 72 + lc + 8) * 2, Kg + 8);                 \
        cp16(sb + VOFF(s) + (lr * 72 + lc) * 2, Vg);                         \
        cp16(sb + VOFF(s) + (lr * 72 + lc + 8) * 2, Vg + 8);                 \
    }

    LOAD_KV(0, 0); cp_commit();
    LOAD_KV(1, 1); cp_commit();

    for (int kb = 0; kb < 64; kb++) {
        const int s = kb % 3;
        cp_wait1();
        __syncthreads();
        if (kb + 2 < 64) LOAD_KV(kb + 2, (kb + 2) % 3);
        cp_commit();

        const uint32_t sK = sb + KOFF(s);
        const uint32_t sV = sb + VOFF(s);

        // S = Qs @ K^T : x4 loads fragment pairs (nt, nt+1)
        float sc[8][4];
#pragma unroll
        for (int nt = 0; nt < 8; nt++) {
            sc[nt][0] = 0.f; sc[nt][1] = 0.f; sc[nt][2] = 0.f; sc[nt][3] = 0.f;
        }
#pragma unroll
        for (int ks = 0; ks < 4; ks++) {
            uint32_t bf[8][2];
#pragma unroll
            for (int np = 0; np < 4; np++) {
                int row = (np * 2 + (mat >> 1)) * 8 + mrow;
                int col = ks * 16 + (mat & 1) * 8;
                uint32_t r4[4];
                ldsm_x4(r4, sK + (row * 72 + col) * 2);
                bf[np * 2][0] = r4[0];     bf[np * 2][1] = r4[1];
                bf[np * 2 + 1][0] = r4[2]; bf[np * 2 + 1][1] = r4[3];
            }
#pragma unroll
            for (int nt = 0; nt < 8; nt++)
                mma16816(sc[nt], qf[ks], bf[nt]);
        }

        // online softmax max-reduce
        float mx0 = -1e30f, mx1 = -1e30f;
#pragma unroll
        for (int nt = 0; nt < 8; nt++) {
            mx0 = fmaxf(mx0, fmaxf(sc[nt][0], sc[nt][1]));
            mx1 = fmaxf(mx1, fmaxf(sc[nt][2], sc[nt][3]));
        }
        mx0 = fmaxf(mx0, __shfl_xor_sync(0xffffffffu, mx0, 1));
        mx0 = fmaxf(mx0, __shfl_xor_sync(0xffffffffu, mx0, 2));
        mx1 = fmaxf(mx1, __shfl_xor_sync(0xffffffffu, mx1, 1));
        mx1 = fmaxf(mx1, __shfl_xor_sync(0xffffffffu, mx1, 2));
        float nm0 = fmaxf(m0, mx0);
        float nm1 = fmaxf(m1, mx1);

        // warp-uniform rescale skip: exact when max is unchanged (cr == 1)
        if (__any_sync(0xffffffffu, (nm0 != m0) | (nm1 != m1))) {
            float cr0 = exp2f(m0 - nm0);
            float cr1 = exp2f(m1 - nm1);
            m0 = nm0;
            m1 = nm1;
            ls[0] *= cr0; ls[1] *= cr0; ls[2] *= cr1; ls[3] *= cr1;
#pragma unroll
            for (int dn = 0; dn < 8; dn++) {
                of[dn][0] *= cr0; of[dn][1] *= cr0;
                of[dn][2] *= cr1; of[dn][3] *= cr1;
            }
        }

        // P = exp2(S - m) in fp16x2 (A-fragment layout)
        uint32_t pf[4][4];
#pragma unroll
        for (int kp = 0; kp < 4; kp++) {
            pf[kp][0] = h2exp2(pack_h2(sc[2 * kp][0] - nm0,     sc[2 * kp][1] - nm0));
            pf[kp][1] = h2exp2(pack_h2(sc[2 * kp][2] - nm1,     sc[2 * kp][3] - nm1));
            pf[kp][2] = h2exp2(pack_h2(sc[2 * kp + 1][0] - nm0, sc[2 * kp + 1][1] - nm0));
            pf[kp][3] = h2exp2(pack_h2(sc[2 * kp + 1][2] - nm1, sc[2 * kp + 1][3] - nm1));
        }

        // row sums via ones-MMA
#pragma unroll
        for (int kp = 0; kp < 4; kp++)
            mma16816(ls, pf[kp], onesb);

        // O += P @ V : x4.trans loads fragment pairs (dn, dn+1)
#pragma unroll
        for (int kp = 0; kp < 4; kp++) {
            uint32_t vf[8][2];
#pragma unroll
            for (int dp = 0; dp < 4; dp++) {
                int row = kp * 16 + (mat & 1) * 8 + mrow;
                int col = (dp * 2 + (mat >> 1)) * 8;
                uint32_t r4[4];
                ldsm_x4t(r4, sV + (row * 72 + col) * 2);
                vf[dp * 2][0] = r4[0];     vf[dp * 2][1] = r4[1];
                vf[dp * 2 + 1][0] = r4[2]; vf[dp * 2 + 1][1] = r4[3];
            }
#pragma unroll
            for (int dn = 0; dn < 8; dn++)
                mma16816(of[dn], pf[kp], vf[dn]);
        }
    }

    // epilogue
    float inv0 = 1.f / ls[0];
    float inv1 = 1.f / ls[2];
    __half* Ob = O + ((size_t)b * 2048 + q0) * GN + h * 64;
#pragma unroll
    for (int dn = 0; dn < 8; dn++) {
        int col = dn * 8 + qd * 2;
        *reinterpret_cast<uint32_t*>(Ob + (size_t)g * GN + col) =
            pack_h2(of[dn][0] * inv0, of[dn][1] * inv0);
        *reinterpret_cast<uint32_t*>(Ob + (size_t)(g + 8) * GN + col) =
            pack_h2(of[dn][2] * inv1, of[dn][3] * inv1);
    }
}

// ---------------------------------------------------------------------------
extern "C" void kernel_launch(void* const* d_in, const int* in_sizes, int n_in,
                              void* d_out, int out_size)
{
    const float* x   = (const float*)d_in[0];
    const float* ctx = (const float*)d_in[1];
    const float* W0  = (const float*)d_in[2];   // Wq
    const float* b0  = (const float*)d_in[3];
    const float* W1  = (const float*)d_in[4];   // Wks
    const float* b1  = (const float*)d_in[5];
    const float* W2  = (const float*)d_in[6];   // Wvs
    const float* b2  = (const float*)d_in[7];
    const float* W3  = (const float*)d_in[8];   // Wkc
    const float* b3  = (const float*)d_in[9];
    const float* W4  = (const float*)d_in[10];  // Wvc
    const float* b4  = (const float*)d_in[11];
    const float* W5  = (const float*)d_in[12];  // Wo
    const float* b5  = (const float*)d_in[13];
    float* out = (float*)d_out;

    __half* xh;
    __half* ch;
    __half* Wt;
    __half* Qh;
    __half* Kh;
    __half* Vh;
    __half* Oh;
    cudaGetSymbolAddress((void**)&xh, g_xh);
    cudaGetSymbolAddress((void**)&ch, g_ch);
    cudaGetSymbolAddress((void**)&Wt, g_Wt);
    cudaGetSymbolAddress((void**)&Qh, g_Qh);
    cudaGetSymbolAddress((void**)&Kh, g_Kh);
    cudaGetSymbolAddress((void**)&Vh, g_Vh);
    cudaGetSymbolAddress((void**)&Oh, g_Oh);

    // launch 0: fp32 -> fp16 inputs (fused)
    dim3 fgrid(4096, 1, 2);
    f2h2_kernel<<<fgrid, 256>>>(x, ctx, xh, ch, 1048576);

    // launch 1: weights transpose-convert (fused)
    dim3 wgrid(32, 32, 6);
    dim3 wblk(32, 8);
    wtrans6_kernel<<<wgrid, wblk>>>(W0, W1, W2, W3, W4, W5, Wt);

    cudaFuncSetAttribute(hgemm_kernel,
                         cudaFuncAttributeMaxDynamicSharedMemorySize, SM_GEMM);
    cudaFuncSetAttribute(hgemm2_kernel,
                         cudaFuncAttributeMaxDynamicSharedMemorySize, SM_GEMM);
    cudaFuncSetAttribute(attn_hmma_kernel,
                         cudaFuncAttributeMaxDynamicSharedMemorySize, SM_ATTN);

    dim3 ggrid(8, 32);
    dim3 ggrid2(8, 32, 2);
    const float qscale = 0.125f * 1.4426950408889634f;  // 1/sqrt(hd) * log2(e)

    // launch 2: Q projection
    hgemm_kernel<<<ggrid, 512, SM_GEMM>>>(xh, Wt + 0u * 1048576u, b0, Qh, nullptr, 0, 2048, 0, qscale);
    // launch 3: K projection (self + context fused)
    hgemm2_kernel<<<ggrid2, 512, SM_GEMM>>>(xh, ch, Wt + 1u * 1048576u, Wt + 3u * 1048576u, b1, b3, Kh);
    // launch 4: V projection (self + context fused)
    hgemm2_kernel<<<ggrid2, 512, SM_GEMM>>>(xh, ch, Wt + 2u * 1048576u, Wt + 4u * 1048576u, b2, b4, Vh);

    // launch 5: attention
    dim3 agrid(16, 16, 2);
    attn_hmma_kernel<<<agrid, 256, SM_ATTN>>>(Qh, Kh, Vh, Oh);

    // launch 6: output projection (fp32 out)
    hgemm_kernel<<<ggrid, 512, SM_GEMM>>>(Oh, Wt + 5u * 1048576u, b5, nullptr, out, 1, 2048, 0, 1.0f);
}

// round 10
// speedup vs baseline: 6.8038x; 1.0503x over previous
#include <cuda_runtime.h>
#include <cuda_fp16.h>
#include <stdint.h>
#include <math.h>

// Shapes: B=2, Tq=2048, Tctx=2048 -> Tk=4096, D=1024, H=16, hd=64
#define GK 1024
#define GN 1024

// ---------------- persistent fp16 scratch ----------------
__device__ __half g_xh[4194304];            // x fp16    [4096][1024]
__device__ __half g_ch[4194304];            // ctx fp16  [4096][1024]
__device__ __half g_Wt[6][1048576];         // W^T fp16  [1024 n][1024 k]
__device__ __half g_Qh[4194304];            // Q (scaled)[2*2048][1024]
__device__ __half g_Kh[8388608];            // K concat  [2*4096][1024]
__device__ __half g_Vh[8388608];            // V concat  [2*4096][1024]
__device__ __half g_Oh[4194304];            // attn out  [2*2048][1024]

// ---------------- ptx helpers ----------------
__device__ __forceinline__ uint32_t smem_u32(const void* p) {
    return static_cast<uint32_t>(__cvta_generic_to_shared(p));
}
__device__ __forceinline__ void cp16(uint32_t dst, const void* src) {
    asm volatile("cp.async.cg.shared.global [%0], [%1], 16;" :: "r"(dst), "l"(src));
}
__device__ __forceinline__ void cp_commit() {
    asm volatile("cp.async.commit_group;" ::: "memory");
}
__device__ __forceinline__ void cp_wait1() {
    asm volatile("cp.async.wait_group 1;" ::: "memory");
}
__device__ __forceinline__ void ldsm_x4(uint32_t* r, uint32_t addr) {
    asm volatile("ldmatrix.sync.aligned.m8n8.x4.shared.b16 {%0,%1,%2,%3}, [%4];"
                 : "=r"(r[0]), "=r"(r[1]), "=r"(r[2]), "=r"(r[3]) : "r"(addr));
}
__device__ __forceinline__ void ldsm_x4t(uint32_t* r, uint32_t addr) {
    asm volatile("ldmatrix.sync.aligned.m8n8.x4.trans.shared.b16 {%0,%1,%2,%3}, [%4];"
                 : "=r"(r[0]), "=r"(r[1]), "=r"(r[2]), "=r"(r[3]) : "r"(addr));
}
__device__ __forceinline__ void mma16816(float* c, const uint32_t* a, const uint32_t* b) {
    asm volatile(
        "mma.sync.aligned.m16n8k16.row.col.f32.f16.f16.f32 "
        "{%0,%1,%2,%3}, {%4,%5,%6,%7}, {%8,%9}, {%0,%1,%2,%3};"
        : "+f"(c[0]), "+f"(c[1]), "+f"(c[2]), "+f"(c[3])
        : "r"(a[0]), "r"(a[1]), "r"(a[2]), "r"(a[3]), "r"(b[0]), "r"(b[1]));
}
__device__ __forceinline__ uint32_t pack_h2(float lo, float hi) {
    __half2 h;
    h.x = __float2half_rn(lo);
    h.y = __float2half_rn(hi);
    uint32_t u;
    memcpy(&u, &h, 4);
    return u;
}
__device__ __forceinline__ uint32_t h2exp2(uint32_t x) {
    uint32_t r;
    asm volatile("ex2.approx.f16x2 %0, %1;" : "=r"(r) : "r"(x));
    return r;
}

// ---------------- fused fp32 -> fp16 convert (z selects tensor) ----------
__global__ void f2h2_kernel(const float* __restrict__ in0, const float* __restrict__ in1,
                            __half* __restrict__ out0, __half* __restrict__ out1, int n4) {
    const float* in = blockIdx.z ? in1 : in0;
    __half* out = blockIdx.z ? out1 : out0;
    int i = blockIdx.x * blockDim.x + threadIdx.x;
    if (i < n4) {
        float4 v = reinterpret_cast<const float4*>(in)[i];
        __half2 a; a.x = __float2half_rn(v.x); a.y = __float2half_rn(v.y);
        __half2 b; b.x = __float2half_rn(v.z); b.y = __float2half_rn(v.w);
        reinterpret_cast<__half2*>(out)[i * 2]     = a;
        reinterpret_cast<__half2*>(out)[i * 2 + 1] = b;
    }
}

// ---------------- fused W [K][N] fp32 -> Wt [N][K] fp16 (z = weight idx) ----
__global__ void wtrans6_kernel(const float* w0, const float* w1, const float* w2,
                               const float* w3, const float* w4, const float* w5,
                               __half* __restrict__ WtBase) {
    __shared__ float t[32][33];
    const float* W;
    switch (blockIdx.z) {
        case 0: W = w0; break;
        case 1: W = w1; break;
        case 2: W = w2; break;
        case 3: W = w3; break;
        case 4: W = w4; break;
        default: W = w5; break;
    }
    __half* Wt = WtBase + (size_t)blockIdx.z * 1048576u;
    int n0 = blockIdx.x * 32, k0 = blockIdx.y * 32;
    int tx = threadIdx.x, ty = threadIdx.y;
#pragma unroll
    for (int i = 0; i < 32; i += 8)
        t[ty + i][tx] = W[(size_t)(k0 + ty + i) * GN + n0 + tx];
    __syncthreads();
#pragma unroll
    for (int i = 0; i < 32; i += 8)
        Wt[(size_t)(n0 + ty + i) * GK + k0 + tx] = __float2half_rn(t[tx][ty + i]);
}

// ---------------- HMMA GEMM, 3-stage cp.async pipeline ----------------
// 512 threads, 16 warps (4m x 4n), warp tile 32x32, CTA tile 128x128, BK=32.
#define TSZ 10240
#define A_OFF(s) ((s) * TSZ)
#define B_OFF(s) (3 * TSZ + (s) * TSZ)
#define SM_GEMM (6 * TSZ)

__device__ __forceinline__ void hgemm_body(
    const __half* __restrict__ A, const __half* __restrict__ Bt,
    const float* __restrict__ bias, __half* __restrict__ outH,
    float* __restrict__ outF, int f32out, int bstride, int roff, float scale,
    char* smem)
{
    const uint32_t sb = smem_u32(smem);
    const int tid = threadIdx.x;
    const int lane = tid & 31;
    const int wid = tid >> 5;                 // 0..15
    const int wm = (wid >> 2) * 32;
    const int wn = (wid & 3) * 32;
    const int row0 = blockIdx.y * 128;
    const int col0 = blockIdx.x * 128;

    const __half* Ag = A + (size_t)row0 * GK;
    const __half* Bg = Bt + (size_t)col0 * GK;

#define GLOAD(kc, s)                                                         \
    {                                                                        \
        int r = tid >> 2;                                                    \
        int cb = (tid & 3) * 8;                                              \
        cp16(sb + A_OFF(s) + r * 80 + cb * 2,                                \
             Ag + (size_t)r * GK + (kc) * 32 + cb);                          \
        cp16(sb + B_OFF(s) + r * 80 + cb * 2,                                \
             Bg + (size_t)r * GK + (kc) * 32 + cb);                          \
    }

    float acc[2][4][4];
#pragma unroll
    for (int i = 0; i < 2; i++)
#pragma unroll
        for (int j = 0; j < 4; j++)
#pragma unroll
            for (int k = 0; k < 4; k++) acc[i][j][k] = 0.f;

    GLOAD(0, 0); cp_commit();
    GLOAD(1, 1); cp_commit();

    const int mat = lane >> 3;
    const int mrow = lane & 7;

    for (int c = 0; c < 32; c++) {
        const int s = c % 3;
        cp_wait1();
        __syncthreads();
        if (c + 2 < 32) GLOAD(c + 2, (c + 2) % 3);
        cp_commit();

#pragma unroll
        for (int ks = 0; ks < 2; ks++) {
            uint32_t af[2][4];
#pragma unroll
            for (int mt = 0; mt < 2; mt++) {
                int row = wm + mt * 16 + (lane & 7) + (lane & 8);
                int col = ks * 16 + (lane >> 4) * 8;
                ldsm_x4(af[mt], sb + A_OFF(s) + (row * 40 + col) * 2);
            }
            uint32_t bf[4][2];
#pragma unroll
            for (int np = 0; np < 2; np++) {
                int row = wn + (np * 2 + (mat >> 1)) * 8 + mrow;
                int col = ks * 16 + (mat & 1) * 8;
                uint32_t r4[4];
                ldsm_x4(r4, sb + B_OFF(s) + (row * 40 + col) * 2);
                bf[np * 2][0] = r4[0];     bf[np * 2][1] = r4[1];
                bf[np * 2 + 1][0] = r4[2]; bf[np * 2 + 1][1] = r4[3];
            }
#pragma unroll
            for (int mt = 0; mt < 2; mt++)
#pragma unroll
                for (int nt = 0; nt < 4; nt++)
                    mma16816(acc[mt][nt], af[mt], bf[nt]);
        }
    }

    const int g = lane >> 2;
    const int qd = lane & 3;
#pragma unroll
    for (int mt = 0; mt < 2; mt++) {
        int r0 = row0 + wm + mt * 16 + g;
        int r1 = r0 + 8;
        size_t or0 = (size_t)((r0 >> 11) * bstride + (r0 & 2047) + roff);
        size_t or1 = (size_t)((r1 >> 11) * bstride + (r1 & 2047) + roff);
#pragma unroll
        for (int nt = 0; nt < 4; nt++) {
            int col = col0 + wn + nt * 8 + qd * 2;
            float b0 = bias[col];
            float b1 = bias[col + 1];
            float v00 = (acc[mt][nt][0] + b0) * scale;
            float v01 = (acc[mt][nt][1] + b1) * scale;
            float v10 = (acc[mt][nt][2] + b0) * scale;
            float v11 = (acc[mt][nt][3] + b1) * scale;
            if (f32out) {
                outF[or0 * GN + col]     = v00;
                outF[or0 * GN + col + 1] = v01;
                outF[or1 * GN + col]     = v10;
                outF[or1 * GN + col + 1] = v11;
            } else {
                *reinterpret_cast<uint32_t*>(&outH[or0 * GN + col]) = pack_h2(v00, v01);
                *reinterpret_cast<uint32_t*>(&outH[or1 * GN + col]) = pack_h2(v10, v11);
            }
        }
    }
}

// all 5 input projections in one launch; blockIdx.z selects the GEMM
__global__ __launch_bounds__(512, 2) void hgemm5_kernel(
    const __half* __restrict__ xh, const __half* __restrict__ ch,
    const __half* __restrict__ WtBase,
    const float* __restrict__ b0, const float* __restrict__ b1,
    const float* __restrict__ b2, const float* __restrict__ b3,
    const float* __restrict__ b4,
    __half* __restrict__ Qh, __half* __restrict__ Kh, __half* __restrict__ Vh,
    float qscale)
{
    extern __shared__ char smem[];
    switch (blockIdx.z) {
        case 0:  // Q = x @ Wq (scaled)
            hgemm_body(xh, WtBase + 0u * 1048576u, b0, Qh, nullptr, 0, 2048, 0, qscale, smem);
            break;
        case 1:  // K self
            hgemm_body(xh, WtBase + 1u * 1048576u, b1, Kh, nullptr, 0, 4096, 0, 1.0f, smem);
            break;
        case 2:  // K context (Wkc = W idx 3)
            hgemm_body(ch, WtBase + 3u * 1048576u, b3, Kh, nullptr, 0, 4096, 2048, 1.0f, smem);
            break;
        case 3:  // V self (Wvs = W idx 2)
            hgemm_body(xh, WtBase + 2u * 1048576u, b2, Vh, nullptr, 0, 4096, 0, 1.0f, smem);
            break;
        default: // V context (Wvc = W idx 4)
            hgemm_body(ch, WtBase + 4u * 1048576u, b4, Vh, nullptr, 0, 4096, 2048, 1.0f, smem);
            break;
    }
}

__global__ __launch_bounds__(512, 2) void hgemm_kernel(
    const __half* __restrict__ A, const __half* __restrict__ Bt,
    const float* __restrict__ bias, __half* __restrict__ outH,
    float* __restrict__ outF, int f32out, int bstride, int roff, float scale)
{
    extern __shared__ char smem[];
    hgemm_body(A, Bt, bias, outH, outF, f32out, bstride, roff, scale, smem);
}

// ---------------- flash attention (HMMA) ----------------
// 3-stage cp.async K/V ring, x4 ldmatrix, fp16x2 exp, ones-MMA row sums,
// warp-vote fast path: skip shuffles + rescale when no lane sees a new max.
#define KVSTG 18432
#define KOFF(s) ((s) * KVSTG)
#define VOFF(s) ((s) * KVSTG + 9216)
#define SM_ATTN (3 * KVSTG)

__global__ __launch_bounds__(256, 2) void attn_hmma_kernel(
    const __half* __restrict__ Q, const __half* __restrict__ K,
    const __half* __restrict__ V, __half* __restrict__ O)
{
    extern __shared__ char smem[];
    const uint32_t sb = smem_u32(smem);

    const int tid = threadIdx.x;
    const int lane = tid & 31;
    const int wid = tid >> 5;
    const int qt = blockIdx.x;
    const int h = blockIdx.y;
    const int b = blockIdx.z;
    const int q0 = qt * 128 + wid * 16;
    const int g = lane >> 2;
    const int qd = lane & 3;
    const int mat = lane >> 3;
    const int mrow = lane & 7;

    const __half* Qb = Q + ((size_t)b * 2048 + q0) * GN + h * 64;
    const __half* Kb = K + (size_t)b * 4096 * GN + h * 64;
    const __half* Vb = V + (size_t)b * 4096 * GN + h * 64;

    // Q fragments (A operand)
    uint32_t qf[4][4];
#pragma unroll
    for (int ks = 0; ks < 4; ks++) {
        int c0 = ks * 16 + qd * 2;
        qf[ks][0] = *reinterpret_cast<const uint32_t*>(Qb + (size_t)g * GN + c0);
        qf[ks][1] = *reinterpret_cast<const uint32_t*>(Qb + (size_t)(g + 8) * GN + c0);
        qf[ks][2] = *reinterpret_cast<const uint32_t*>(Qb + (size_t)g * GN + c0 + 8);
        qf[ks][3] = *reinterpret_cast<const uint32_t*>(Qb + (size_t)(g + 8) * GN + c0 + 8);
    }

    float of[8][4];
#pragma unroll
    for (int i = 0; i < 8; i++)
#pragma unroll
        for (int j = 0; j < 4; j++) of[i][j] = 0.f;
    float ls[4] = {0.f, 0.f, 0.f, 0.f};
    float m0 = -1e30f, m1 = -1e30f;

    const uint32_t ONES2 = 0x3C003C00u;
    const uint32_t onesb[2] = {ONES2, ONES2};

    const int lr = tid & 63;
    const int lc = (tid >> 6) * 16;

#define LOAD_KV(kb, s)                                                       \
    {                                                                        \
        const __half* Kg = Kb + (size_t)((kb) * 64 + lr) * GN + lc;          \
        const __half* Vg = Vb + (size_t)((kb) * 64 + lr) * GN + lc;          \
        cp16(sb + KOFF(s) + (lr * 72 + lc) * 2, Kg);                         \
        cp16(sb + KOFF(s) + (lr * 72 + lc + 8) * 2, Kg + 8);                 \
        cp16(sb + VOFF(s) + (lr * 72 + lc) * 2, Vg);                         \
        cp16(sb + VOFF(s) + (lr * 72 + lc + 8) * 2, Vg + 8);                 \
    }

    LOAD_KV(0, 0); cp_commit();
    LOAD_KV(1, 1); cp_commit();

    for (int kb = 0; kb < 64; kb++) {
        const int s = kb % 3;
        cp_wait1();
        __syncthreads();
        if (kb + 2 < 64) LOAD_KV(kb + 2, (kb + 2) % 3);
        cp_commit();

        const uint32_t sK = sb + KOFF(s);
        const uint32_t sV = sb + VOFF(s);

        // S = Qs @ K^T : x4 loads fragment pairs (nt, nt+1)
        float sc[8][4];
#pragma unroll
        for (int nt = 0; nt < 8; nt++) {
            sc[nt][0] = 0.f; sc[nt][1] = 0.f; sc[nt][2] = 0.f; sc[nt][3] = 0.f;
        }
#pragma unroll
        for (int ks = 0; ks < 4; ks++) {
            uint32_t bf[8][2];
#pragma unroll
            for (int np = 0; np < 4; np++) {
                int row = (np * 2 + (mat >> 1)) * 8 + mrow;
                int col = ks * 16 + (mat & 1) * 8;
                uint32_t r4[4];
                ldsm_x4(r4, sK + (row * 72 + col) * 2);
                bf[np * 2][0] = r4[0];     bf[np * 2][1] = r4[1];
                bf[np * 2 + 1][0] = r4[2]; bf[np * 2 + 1][1] = r4[3];
            }
#pragma unroll
            for (int nt = 0; nt < 8; nt++)
                mma16816(sc[nt], qf[ks], bf[nt]);
        }

        // local max (per-lane over 16 values)
        float mx0 = -1e30f, mx1 = -1e30f;
#pragma unroll
        for (int nt = 0; nt < 8; nt++) {
            mx0 = fmaxf(mx0, fmaxf(sc[nt][0], sc[nt][1]));
            mx1 = fmaxf(mx1, fmaxf(sc[nt][2], sc[nt][3]));
        }

        // warp-vote fast path: if NO lane sees a value above its running max,
        // the quad maxima cannot exceed m either -> skip shuffles + rescale.
        if (__any_sync(0xffffffffu, (mx0 > m0) | (mx1 > m1))) {
            mx0 = fmaxf(mx0, __shfl_xor_sync(0xffffffffu, mx0, 1));
            mx0 = fmaxf(mx0, __shfl_xor_sync(0xffffffffu, mx0, 2));
            mx1 = fmaxf(mx1, __shfl_xor_sync(0xffffffffu, mx1, 1));
            mx1 = fmaxf(mx1, __shfl_xor_sync(0xffffffffu, mx1, 2));
            float nm0 = fmaxf(m0, mx0);
            float nm1 = fmaxf(m1, mx1);
            float cr0 = exp2f(m0 - nm0);
            float cr1 = exp2f(m1 - nm1);
            m0 = nm0;
            m1 = nm1;
            ls[0] *= cr0; ls[1] *= cr0; ls[2] *= cr1; ls[3] *= cr1;
#pragma unroll
            for (int dn = 0; dn < 8; dn++) {
                of[dn][0] *= cr0; of[dn][1] *= cr0;
                of[dn][2] *= cr1; of[dn][3] *= cr1;
            }
        }

        // P = exp2(S - m) in fp16x2 (A-fragment layout); subtract in fp32
        uint32_t pf[4][4];
#pragma unroll
        for (int kp = 0; kp < 4; kp++) {
            pf[kp][0] = h2exp2(pack_h2(sc[2 * kp][0] - m0,     sc[2 * kp][1] - m0));
            pf[kp][1] = h2exp2(pack_h2(sc[2 * kp][2] - m1,     sc[2 * kp][3] - m1));
            pf[kp][2] = h2exp2(pack_h2(sc[2 * kp + 1][0] - m0, sc[2 * kp + 1][1] - m0));
            pf[kp][3] = h2exp2(pack_h2(sc[2 * kp + 1][2] - m1, sc[2 * kp + 1][3] - m1));
        }

        // row sums via ones-MMA
#pragma unroll
        for (int kp = 0; kp < 4; kp++)
            mma16816(ls, pf[kp], onesb);

        // O += P @ V : x4.trans loads fragment pairs (dn, dn+1)
#pragma unroll
        for (int kp = 0; kp < 4; kp++) {
            uint32_t vf[8][2];
#pragma unroll
            for (int dp = 0; dp < 4; dp++) {
                int row = kp * 16 + (mat & 1) * 8 + mrow;
                int col = (dp * 2 + (mat >> 1)) * 8;
                uint32_t r4[4];
                ldsm_x4t(r4, sV + (row * 72 + col) * 2);
                vf[dp * 2][0] = r4[0];     vf[dp * 2][1] = r4[1];
                vf[dp * 2 + 1][0] = r4[2]; vf[dp * 2 + 1][1] = r4[3];
            }
#pragma unroll
            for (int dn = 0; dn < 8; dn++)
                mma16816(of[dn], pf[kp], vf[dn]);
        }
    }

    // epilogue
    float inv0 = 1.f / ls[0];
    float inv1 = 1.f / ls[2];
    __half* Ob = O + ((size_t)b * 2048 + q0) * GN + h * 64;
#pragma unroll
    for (int dn = 0; dn < 8; dn++) {
        int col = dn * 8 + qd * 2;
        *reinterpret_cast<uint32_t*>(Ob + (size_t)g * GN + col) =
            pack_h2(of[dn][0] * inv0, of[dn][1] * inv0);
        *reinterpret_cast<uint32_t*>(Ob + (size_t)(g + 8) * GN + col) =
            pack_h2(of[dn][2] * inv1, of[dn][3] * inv1);
    }
}

// ---------------------------------------------------------------------------
extern "C" void kernel_launch(void* const* d_in, const int* in_sizes, int n_in,
                              void* d_out, int out_size)
{
    const float* x   = (const float*)d_in[0];
    const float* ctx = (const float*)d_in[1];
    const float* W0  = (const float*)d_in[2];   // Wq
    const float* b0  = (const float*)d_in[3];
    const float* W1  = (const float*)d_in[4];   // Wks
    const float* b1  = (const float*)d_in[5];
    const float* W2  = (const float*)d_in[6];   // Wvs
    const float* b2  = (const float*)d_in[7];
    const float* W3  = (const float*)d_in[8];   // Wkc
    const float* b3  = (const float*)d_in[9];
    const float* W4  = (const float*)d_in[10];  // Wvc
    const float* b4  = (const float*)d_in[11];
    const float* W5  = (const float*)d_in[12];  // Wo
    const float* b5  = (const float*)d_in[13];
    float* out = (float*)d_out;

    __half* xh;
    __half* ch;
    __half* Wt;
    __half* Qh;
    __half* Kh;
    __half* Vh;
    __half* Oh;
    cudaGetSymbolAddress((void**)&xh, g_xh);
    cudaGetSymbolAddress((void**)&ch, g_ch);
    cudaGetSymbolAddress((void**)&Wt, g_Wt);
    cudaGetSymbolAddress((void**)&Qh, g_Qh);
    cudaGetSymbolAddress((void**)&Kh, g_Kh);
    cudaGetSymbolAddress((void**)&Vh, g_Vh);
    cudaGetSymbolAddress((void**)&Oh, g_Oh);

    // launch 0: fp32 -> fp16 inputs (fused)
    dim3 fgrid(4096, 1, 2);
    f2h2_kernel<<<fgrid, 256>>>(x, ctx, xh, ch, 1048576);

    // launch 1: weights transpose-convert (fused)
    dim3 wgrid(32, 32, 6);
    dim3 wblk(32, 8);
    wtrans6_kernel<<<wgrid, wblk>>>(W0, W1, W2, W3, W4, W5, Wt);

    cudaFuncSetAttribute(hgemm5_kernel,
                         cudaFuncAttributeMaxDynamicSharedMemorySize, SM_GEMM);
    cudaFuncSetAttribute(hgemm_kernel,
                         cudaFuncAttributeMaxDynamicSharedMemorySize, SM_GEMM);
    cudaFuncSetAttribute(attn_hmma_kernel,
                         cudaFuncAttributeMaxDynamicSharedMemorySize, SM_ATTN);

    const float qscale = 0.125f * 1.4426950408889634f;  // 1/sqrt(hd) * log2(e)

    // launch 2: all 5 input projections fused (Q, Ks, Kc, Vs, Vc)
    dim3 ggrid5(8, 32, 5);
    hgemm5_kernel<<<ggrid5, 512, SM_GEMM>>>(xh, ch, Wt, b0, b1, b2, b3, b4,
                                            Qh, Kh, Vh, qscale);

    // launch 3: attention
    dim3 agrid(16, 16, 2);
    attn_hmma_kernel<<<agrid, 256, SM_ATTN>>>(Qh, Kh, Vh, Oh);

    // launch 4: output projection (fp32 out)
    dim3 ggrid(8, 32);
    hgemm_kernel<<<ggrid, 512, SM_GEMM>>>(Oh, Wt + 5u * 1048576u, b5, nullptr, out, 1, 2048, 0, 1.0f);
}